// round 13
// baseline (speedup 1.0000x reference)
#include <cuda_runtime.h>
#include <math.h>
#include <stdint.h>

// Problem constants
#define BB 2
#define CC 4
#define HH 256
#define WW 256
#define FF 128
#define NPIX (HH*WW)                 // 65536
#define NTOT (BB*CC*NPIX)            // 524288
#define NHID (2*BB*FF*NPIX)          // both branches: 33554432 floats (134MB)

typedef unsigned long long u64;
typedef unsigned int u32;

// ---------------- scratch (device globals; no allocation allowed) -------------
__device__ float g_stateA[NTOT];
__device__ float g_stateB[NTOT];
__device__ float g_hid[NHID];        // hidden activations, [branch*BB+b][128][HW]
__device__ float g_upd[NTOT];
__device__ float g_nbr[NTOT];
__device__ float g_sim[NTOT];
__device__ float g_boxst[NTOT];
__device__ float g_gfeat[BB*CC];
__device__ float g_scale[BB*CC];
__device__ float g_simsum[BB*CC];
__device__ float g_loss;
__device__ unsigned g_ticket;        // last-block ticket for gfeat->scale fusion

__device__ __forceinline__ float sigm(float v) { return 1.f/(1.f+expf(-v)); }

// ---------------- f32x2 helpers -----------------------------------------------
__device__ __forceinline__ u64 pack2(float lo, float hi) {
    u64 r; asm("mov.b64 %0, {%1, %2};" : "=l"(r) : "f"(lo), "f"(hi)); return r;
}
__device__ __forceinline__ u64 dup2(float v) { return pack2(v, v); }
__device__ __forceinline__ void fma2(u64& d, u64 a, u64 b) {
    asm("fma.rn.f32x2 %0, %1, %2, %0;" : "+l"(d) : "l"(a), "l"(b));
}
__device__ __forceinline__ float lo2(u64 v) { return __uint_as_float((unsigned)(v & 0xffffffffu)); }
__device__ __forceinline__ float hi2(u64 v) { return __uint_as_float((unsigned)(v >> 32)); }

// ---------------- gfeat + scale fused (last-block pattern) --------------------
__global__ void k_gfeat_scale(const float* __restrict__ x,
                              const float* __restrict__ fc_w,
                              const float* __restrict__ fc_b,
                              const float* __restrict__ modw)
{
    __shared__ float red[256];
    __shared__ unsigned s_last;
    int bc = blockIdx.x;
    const float* p = x + (size_t)bc*NPIX;
    float s = 0.f;
    for (int i = threadIdx.x; i < NPIX; i += 256) s += p[i];
    red[threadIdx.x] = s; __syncthreads();
    for (int o = 128; o > 0; o >>= 1) { if (threadIdx.x < o) red[threadIdx.x] += red[threadIdx.x+o]; __syncthreads(); }
    if (threadIdx.x == 0) {
        g_gfeat[bc] = red[0] * (1.f/(float)NPIX);
        __threadfence();
        s_last = atomicAdd(&g_ticket, 1u);
    }
    __syncthreads();
    if (s_last == BB*CC - 1) {   // last block computes scales
        int t = threadIdx.x;
        if (t < BB*CC) {
            int b = t / CC, c = t % CC;
            float z = fc_b[c];
            #pragma unroll
            for (int j = 0; j < CC; j++) z += g_gfeat[b*CC+j] * fc_w[c*CC+j];
            g_scale[t] = sigm(z) * sigm(modw[c]);
        }
        if (t == 0) { g_loss = 0.f; g_ticket = 0u; }  // reset for next graph replay
    }
}

// ---------------- state init ---------------------------------------------------
__global__ void k_init(const float* __restrict__ x)
{
    int i = blockIdx.x*256 + threadIdx.x;
    if (i < NTOT) g_stateA[i] = x[i] * g_scale[i >> 16];
}

// ---------------- conv 4 -> 128, 3x3, BOTH branches (runtime dilation) --------
// grid (8,16,4): z = br*BB + b. S = 1+br. Tile 32x16 px, 2 px/thread.
// AT FFMA2 ROOFLINE — do not touch.
__global__ void __launch_bounds__(256) k_c2f(
    const float* __restrict__ state,
    const float* __restrict__ w_su, const float* __restrict__ b_su,
    const float* __restrict__ w_nu, const float* __restrict__ b_nu)
{
    constexpr int TW = 36, TH = 20;     // worst case halo (S=2)
    __shared__ float s_wt[36*FF];       // [j][oc] transposed
    __shared__ float s_b[FF];
    __shared__ float s_in[CC*TH*TW];
    const int tid = threadIdx.x;
    const int z = blockIdx.z;
    const int br = z >> 1, b = z & 1;
    const int S = 1 + br;
    const float* w    = br ? w_nu : w_su;
    const float* bias = br ? b_nu : b_su;
    const int x0 = blockIdx.x*32, y0 = blockIdx.y*16;

    // zero simsum once per grid (before iter_a of this iteration)
    if (blockIdx.x == 0 && blockIdx.y == 0 && z == 0 && tid < BB*CC) g_simsum[tid] = 0.f;

    for (int i = tid; i < 36*FF; i += 256) {
        int oc = i & 127, j = i >> 7;
        s_wt[i] = w[oc*36 + j];
    }
    if (tid < FF) s_b[tid] = bias[tid];
    for (int i = tid; i < CC*TH*TW; i += 256) {
        int c = i/(TH*TW), r = i%(TH*TW);
        int sy = r/TW, sx = r%TW;
        int gy = y0+sy-S, gx = x0+sx-S;
        float v = 0.f;
        if (gy >= 0 && gy < HH && gx >= 0 && gx < WW)
            v = state[((size_t)(b*CC+c) << 16) + (gy<<8) + gx];
        s_in[i] = v;
    }
    __syncthreads();

    const int tx = tid & 15, ty = tid >> 4;
    const int lx = (S == 1) ? 2*tx : ((tx & 1) + (tx >> 1)*4);
    const int gx0 = x0 + lx, gy = y0 + ty;

    u64 dup[48];
    #pragma unroll
    for (int c = 0; c < 4; c++)
        #pragma unroll
        for (int r = 0; r < 3; r++)
            #pragma unroll
            for (int k = 0; k < 4; k++)
                dup[c*12 + r*4 + k] = dup2(s_in[(c*TH + ty + r*S)*TW + lx + k*S]);

    float* outp = g_hid + ((size_t)z*FF << 16) + (gy<<8) + gx0;
    #pragma unroll 2
    for (int op = 0; op < 64; op++) {
        u64 a0 = *(const u64*)&s_b[2*op];
        u64 a1 = a0;
        #pragma unroll
        for (int c = 0; c < 4; c++)
            #pragma unroll
            for (int ky = 0; ky < 3; ky++)
                #pragma unroll
                for (int kx = 0; kx < 3; kx++) {
                    u64 w2 = *(const u64*)&s_wt[(c*9 + ky*3 + kx)*FF + 2*op];
                    fma2(a0, dup[c*12 + ky*4 + kx],     w2);
                    fma2(a1, dup[c*12 + ky*4 + kx + 1], w2);
                }
        outp[(size_t)(2*op)   << 16]       = fmaxf(lo2(a0), 0.f);
        outp[(size_t)(2*op+1) << 16]       = fmaxf(hi2(a0), 0.f);
        outp[((size_t)(2*op)   << 16) + S] = fmaxf(lo2(a1), 0.f);
        outp[((size_t)(2*op+1) << 16) + S] = fmaxf(hi2(a1), 0.f);
    }
}

// ---------------- conv 128 -> 4, 3x3 — 4 px/thread + cp.async staging ---------
// R9/R11 compute loop (unchanged math). Staging now cp.async into ping-pong
// smem buffers: no pre[] registers, no per-thread load waits. One sync/chunk.
template<int S>
__device__ __forceinline__ void f2c_stage(
    u32 sbuf_u32, const float* __restrict__ nb, int x0, int y0, int tid)
{
    constexpr int TW = 36, TH = 20, CH = 4;
    constexpr int NACT = CH*TH*TW;      // 2880
    for (int i = tid; i < NACT; i += 128) {
        int c = i/(TH*TW), r = i%(TH*TW), sy = r/TW, sx = r%TW;
        int gy = y0+sy-S, gx = x0+sx-S;
        bool ok = (gy >= 0 && gy < HH && gx >= 0 && gx < WW);
        const float* gp = ok ? nb + (((size_t)c << 16) + (gy<<8) + gx) : nb;
        asm volatile("cp.async.ca.shared.global [%0], [%1], 4, %2;"
                     :: "r"(sbuf_u32 + (u32)(i*4)), "l"(gp), "r"(ok ? 4 : 0)
                     : "memory");
    }
    asm volatile("cp.async.commit_group;" ::: "memory");
}

template<int S>
__device__ __forceinline__ void f2c_run(
    float* s_act, float* s_w,
    const float* __restrict__ bias,
    const float* __restrict__ actbase, float* __restrict__ out,
    int b, int x0, int y0, int tid)
{
    constexpr int TW = 36, TH = 20;
    constexpr int CH = 4, NCHUNK = FF/CH;   // 32 chunks
    constexpr int NACT = CH*TH*TW;          // 2880

    const int tx = tid & 7, ty = tid >> 3;
    const int lx = 4*tx;
    const u32 s_act_u32 = (u32)__cvta_generic_to_shared(s_act);

    u64 a01[4], a23[4];   // per px p: (oc0,oc1) and (oc2,oc3)
    {
        u64 b01 = pack2(bias[0], bias[1]);
        u64 b23 = pack2(bias[2], bias[3]);
        #pragma unroll
        for (int p = 0; p < 4; p++) { a01[p] = b01; a23[p] = b23; }
    }

    // prologue: stage chunk 0 into buffer 0
    f2c_stage<S>(s_act_u32, actbase, x0, y0, tid);

    for (int ck = 0; ck < NCHUNK; ck++) {
        asm volatile("cp.async.wait_group 0;" ::: "memory");
        __syncthreads();
        if (ck + 1 < NCHUNK) {
            const float* nb = actbase + ((size_t)((ck+1)*CH) << 16);
            f2c_stage<S>(s_act_u32 + (u32)(((ck+1) & 1) * NACT * 4), nb, x0, y0, tid);
        }
        const float* buf = s_act + (ck & 1) * NACT;
        #pragma unroll
        for (int c = 0; c < CH; c++) {
            const int ic = ck*CH + c;
            #pragma unroll
            for (int r = 0; r < 3; r++) {
                const float* rowp = &buf[(c*TH + ty + r*S)*TW + lx];
                float4 q0 = *(const float4*)rowp;       // cols lx..lx+3
                float4 q1 = *(const float4*)(rowp + 4); // cols lx+4..lx+7
                u64 dd[8];
                dd[0] = dup2(q0.x); dd[1] = dup2(q0.y);
                dd[2] = dup2(q0.z); dd[3] = dup2(q0.w);
                dd[4] = dup2(q1.x); dd[5] = dup2(q1.y);
                dd[6] = dup2(q1.z); dd[7] = dup2(q1.w);
                #pragma unroll
                for (int k = 0; k < 3; k++) {
                    longlong2 wv = *(const longlong2*)&s_w[(ic*9 + r*3 + k)*4];
                    #pragma unroll
                    for (int p = 0; p < 4; p++) {
                        fma2(a01[p], dd[p + k*S], (u64)wv.x);
                        fma2(a23[p], dd[p + k*S], (u64)wv.y);
                    }
                }
            }
        }
    }

    const int gx0 = x0 + lx, gy = y0 + ty;
    size_t base = ((size_t)b*CC << 16) + (gy<<8) + gx0;
    float4 v0 = make_float4(lo2(a01[0]), lo2(a01[1]), lo2(a01[2]), lo2(a01[3]));
    float4 v1 = make_float4(hi2(a01[0]), hi2(a01[1]), hi2(a01[2]), hi2(a01[3]));
    float4 v2 = make_float4(lo2(a23[0]), lo2(a23[1]), lo2(a23[2]), lo2(a23[3]));
    float4 v3 = make_float4(hi2(a23[0]), hi2(a23[1]), hi2(a23[2]), hi2(a23[3]));
    *(float4*)&out[base]                     = v0;
    *(float4*)&out[base + ((size_t)1 << 16)] = v1;
    *(float4*)&out[base + ((size_t)2 << 16)] = v2;
    *(float4*)&out[base + ((size_t)3 << 16)] = v3;
}

__global__ void __launch_bounds__(128) k_f2c(
    const float* __restrict__ w_su, const float* __restrict__ b_su,
    const float* __restrict__ w_nu, const float* __restrict__ b_nu)
{
    constexpr int NACT = 4*20*36;           // 2880
    extern __shared__ float smem[];
    float* s_act = smem;                    // 2 x 2880 floats (23KB ping-pong)
    float* s_w   = smem + 2*NACT;           // 4608 floats (18KB): [ic][kj][oc]
    const int tid = threadIdx.x;
    const int z = blockIdx.z;
    const int br = z >> 1, b = z & 1;
    const float* w    = br ? w_nu : w_su;
    const float* bias = br ? b_nu : b_su;
    float* out = (br ? g_nbr : g_upd);
    const float* actbase = g_hid + ((size_t)z*FF << 16);
    const int x0 = blockIdx.x*32, y0 = blockIdx.y*16;

    for (int i = tid; i < CC*FF*9; i += 128) {
        int oc = i & 3, t = i >> 2;
        int ic = t / 9, kj = t % 9;
        s_w[i] = w[((size_t)oc*FF + ic)*9 + kj];
    }
    __syncthreads();   // weights ready before compute reads them

    if (br == 0) f2c_run<1>(s_act, s_w, bias, actbase, out, b, x0, y0, tid);
    else         f2c_run<2>(s_act, s_w, bias, actbase, out, b, x0, y0, tid);
}

// ---------------- fused gradient-magnitude + box sums + similarity ------------
__global__ void k_iter_a(const float* __restrict__ state,
                         const float* __restrict__ skx, const float* __restrict__ sky)
{
    __shared__ float s_st[22*22];
    __shared__ float s_gm[20*20];
    __shared__ float red[256];
    const int bc = blockIdx.z;
    const int c = bc & 3;
    const int x0 = blockIdx.x*16, y0 = blockIdx.y*16;
    const int tid = threadIdx.x;
    const float* sp = state + ((size_t)bc << 16);

    for (int i = tid; i < 22*22; i += 256) {
        int sy = i/22, sx = i%22;
        int gy = y0+sy-3, gx = x0+sx-3;
        float v = 0.f;
        if (gy >= 0 && gy < HH && gx >= 0 && gx < WW) v = sp[(gy<<8) + gx];
        s_st[i] = v;
    }
    float kx[9], ky[9];
    #pragma unroll
    for (int j = 0; j < 9; j++) { kx[j] = skx[c*9+j]; ky[j] = sky[c*9+j]; }
    __syncthreads();

    for (int i = tid; i < 20*20; i += 256) {
        int sy = i/20, sx = i%20;
        int gy = y0+sy-2, gx = x0+sx-2;
        float v = 0.f;
        if (gy >= 0 && gy < HH && gx >= 0 && gx < WW) {
            float ax = 0.f, ay = 0.f;
            #pragma unroll
            for (int dy = 0; dy < 3; dy++)
                #pragma unroll
                for (int dx = 0; dx < 3; dx++) {
                    float s = s_st[(sy+dy)*22 + sx+dx];
                    ax += s * kx[dy*3+dx];
                    ay += s * ky[dy*3+dx];
                }
            v = sqrtf(ax*ax + ay*ay);
        }
        s_gm[i] = v;
    }
    __syncthreads();

    const int tx = tid & 15, ty = tid >> 4;
    float g0 = s_gm[(ty+2)*20 + tx+2];
    float s1 = 0.f, s2 = 0.f, s3 = 0.f;
    #pragma unroll
    for (int dy = 0; dy < 5; dy++)
        #pragma unroll
        for (int dx = 0; dx < 5; dx++) {
            float g = s_gm[(ty+dy)*20 + tx+dx];
            s1 += g; s2 += g*g;
            s3 += s_st[(ty+1+dy)*22 + tx+1+dx];
        }
    float dist = s2 - 2.f*g0*s1 + 25.f*g0*g0;
    float sv = expf(-2.f*dist);
    size_t oi = ((size_t)bc << 16) + ((y0+ty)<<8) + (x0+tx);
    g_sim[oi]   = sv;
    g_boxst[oi] = s3;

    red[tid] = sv; __syncthreads();
    for (int o = 128; o > 0; o >>= 1) { if (tid < o) red[tid] += red[tid+o]; __syncthreads(); }
    if (tid == 0) atomicAdd(&g_simsum[bc], red[0]);
}

// ---------------- fused dynamic conv + combine (ping-pong state) --------------
__global__ void k_iter_b(const float* __restrict__ state, float* __restrict__ nstate,
                         const float* __restrict__ w, const float* __restrict__ bias)
{
    __shared__ float s_st[4*18*18];
    __shared__ float s_w[144];
    __shared__ float s_b[4];
    const int b = blockIdx.z;
    const int x0 = blockIdx.x*16, y0 = blockIdx.y*16;
    const int tid = threadIdx.x;

    if (tid < 144) s_w[tid] = w[tid];
    if (tid < 4)   s_b[tid] = bias[tid];
    for (int i = tid; i < 4*18*18; i += 256) {
        int c = i/324, r = i%324, sy = r/18, sx = r%18;
        int gy = y0+sy-1, gx = x0+sx-1;
        float v = 0.f;
        if (gy >= 0 && gy < HH && gx >= 0 && gx < WW)
            v = state[((size_t)(b*4+c) << 16) + (gy<<8) + gx];
        s_st[i] = v;
    }
    __syncthreads();

    const int tx = tid & 15, ty = tid >> 4;
    float hf[4] = { s_b[0], s_b[1], s_b[2], s_b[3] };
    #pragma unroll
    for (int ic = 0; ic < 4; ic++) {
        float v[9];
        #pragma unroll
        for (int dy = 0; dy < 3; dy++)
            #pragma unroll
            for (int dx = 0; dx < 3; dx++)
                v[dy*3+dx] = s_st[ic*324 + (ty+dy)*18 + tx+dx];
        #pragma unroll
        for (int oc = 0; oc < 4; oc++)
            #pragma unroll
            for (int j = 0; j < 9; j++)
                hf[oc] += v[j] * s_w[(oc*4+ic)*9 + j];
    }

    #pragma unroll
    for (int cc = 0; cc < 4; cc++) {
        size_t idx = ((size_t)(b*4+cc) << 16) + ((y0+ty)<<8) + (x0+tx);
        float inv = 1.f/(g_simsum[b*4+cc] + 1e-8f);
        nstate[idx] = g_sim[idx]*inv*g_boxst[idx] + g_upd[idx] + g_nbr[idx] + hf[cc];
    }
}

// ---------------- fused final: gm + hf + selection + loss ---------------------
__global__ void k_final(const float* __restrict__ state, const int* __restrict__ tgt,
                        const float* __restrict__ dw, const float* __restrict__ db,
                        const float* __restrict__ skx, const float* __restrict__ sky,
                        float* __restrict__ out)
{
    __shared__ float s_st[4*18*18];
    __shared__ float s_w[144];
    __shared__ float s_b[4];
    __shared__ float s_k[2*36];
    __shared__ float red[256];
    const int b = blockIdx.z;
    const int x0 = blockIdx.x*16, y0 = blockIdx.y*16;
    const int tid = threadIdx.x;

    if (tid < 144) s_w[tid] = dw[tid];
    if (tid < 4)   s_b[tid] = db[tid];
    if (tid < 36)  s_k[tid] = skx[tid];
    if (tid >= 36 && tid < 72) s_k[tid] = sky[tid-36];
    for (int i = tid; i < 4*18*18; i += 256) {
        int c = i/324, r = i%324, sy = r/18, sx = r%18;
        int gy = y0+sy-1, gx = x0+sx-1;
        float v = 0.f;
        if (gy >= 0 && gy < HH && gx >= 0 && gx < WW)
            v = state[((size_t)(b*4+c) << 16) + (gy<<8) + gx];
        s_st[i] = v;
    }
    __syncthreads();

    const int tx = tid & 15, ty = tid >> 4;
    const int t = tgt[b];
    float lsum = 0.f;

    float hf[4] = { s_b[0], s_b[1], s_b[2], s_b[3] };
    #pragma unroll
    for (int ic = 0; ic < 4; ic++) {
        float v[9];
        #pragma unroll
        for (int dy = 0; dy < 3; dy++)
            #pragma unroll
            for (int dx = 0; dx < 3; dx++)
                v[dy*3+dx] = s_st[ic*324 + (ty+dy)*18 + tx+dx];
        #pragma unroll
        for (int oc = 0; oc < 4; oc++)
            #pragma unroll
            for (int j = 0; j < 9; j++)
                hf[oc] += v[j] * s_w[(oc*4+ic)*9 + j];
    }

    #pragma unroll
    for (int c = 0; c < 4; c++) {
        float ax = 0.f, ay = 0.f;
        #pragma unroll
        for (int dy = 0; dy < 3; dy++)
            #pragma unroll
            for (int dx = 0; dx < 3; dx++) {
                float s = s_st[c*324 + (ty+dy)*18 + tx+dx];
                ax += s * s_k[c*9 + dy*3+dx];
                ay += s * s_k[36 + c*9 + dy*3+dx];
            }
        float gmv = sqrtf(ax*ax + ay*ay);
        float hfs = sigm(hf[c]);
        float sg  = sigm(gmv);
        float pos, neg;
        if      (t == 0) { pos = hfs;     neg = 1.f - sg;      }
        else if (t == 1) { pos = sg;      neg = 1.f - hfs;     }
        else if (t == 2) { pos = hfs*sg;  neg = 1.f - hfs*sg;  }
        else             { float q = sigm(gmv*hfs); pos = q; neg = 1.f - q; }
        pos = fminf(fmaxf(pos, 0.f), 1.f);
        neg = fminf(fmaxf(neg, 0.f), 1.f);
        float ep = expf(pos), en = expf(neg);
        float sel = ep / (ep + en + 1e-8f);
        size_t idx = ((size_t)(b*4+c) << 16) + ((y0+ty)<<8) + (x0+tx);
        out[idx] = state[idx] * sel;
        lsum += sel*neg + (1.f - sel)*pos;
    }

    red[tid] = lsum; __syncthreads();
    for (int o = 128; o > 0; o >>= 1) { if (tid < o) red[tid] += red[tid+o]; __syncthreads(); }
    if (tid == 0) atomicAdd(&g_loss, red[0]);
}

__global__ void k_write_loss(float* __restrict__ out)
{
    if (threadIdx.x == 0) out[NTOT] = g_loss * (1.f/(float)NTOT);
}

// ---------------- launcher -----------------------------------------------------
extern "C" void kernel_launch(void* const* d_in, const int* in_sizes, int n_in,
                              void* d_out, int out_size)
{
    const float* x      = (const float*)d_in[0];
    const int*   tgt    = (const int*)  d_in[1];
    const float* fc_w   = (const float*)d_in[2];
    const float* fc_b   = (const float*)d_in[3];
    const float* modw   = (const float*)d_in[4];
    const float* su_w1  = (const float*)d_in[5];
    const float* su_b1  = (const float*)d_in[6];
    const float* su_w2  = (const float*)d_in[7];
    const float* su_b2  = (const float*)d_in[8];
    const float* nu_w1  = (const float*)d_in[9];
    const float* nu_b1  = (const float*)d_in[10];
    const float* nu_w2  = (const float*)d_in[11];
    const float* nu_b2  = (const float*)d_in[12];
    const float* dc_w   = (const float*)d_in[13];
    const float* dc_b   = (const float*)d_in[14];
    const float* sob_kx = (const float*)d_in[15];
    const float* sob_ky = (const float*)d_in[16];
    float* out = (float*)d_out;

    float *pA, *pB;
    cudaGetSymbolAddress((void**)&pA, g_stateA);
    cudaGetSymbolAddress((void**)&pB, g_stateB);

    // dynamic smem for f2c: 2*2880 + 4608 floats = 41472 B
    const int smemF = (2*2880 + 4608)*4;
    cudaFuncSetAttribute(k_f2c, cudaFuncAttributeMaxDynamicSharedMemorySize, smemF);

    const dim3 cgrid(8, 16, 4);        // conv tiles 32x16, z = branch*BB+b
    const dim3 agrid(16, 16, BB*CC);   // iter_a tiles 16x16 per (b,c)
    const dim3 bgrid(16, 16, BB);      // iter_b / final tiles 16x16 per b
    const int PW = (NTOT + 255)/256;

    k_gfeat_scale<<<BB*CC, 256>>>(x, fc_w, fc_b, modw);
    k_init<<<PW, 256>>>(x);

    float* cur = pA;
    float* nxt = pB;
    for (int it = 0; it < 3; it++) {
        k_c2f<<<cgrid, 256>>>(cur, su_w1, su_b1, nu_w1, nu_b1);
        k_f2c<<<cgrid, 128, smemF>>>(su_w2, su_b2, nu_w2, nu_b2);
        k_iter_a<<<agrid, 256>>>(cur, sob_kx, sob_ky);
        k_iter_b<<<bgrid, 256>>>(cur, nxt, dc_w, dc_b);
        float* tmpp = cur; cur = nxt; nxt = tmpp;
    }

    k_final<<<bgrid, 256>>>(cur, tgt, dc_w, dc_b, sob_kx, sob_ky, out);
    if (out_size > NTOT) k_write_loss<<<1, 32>>>(out);
}

// round 14
// speedup vs baseline: 1.1637x; 1.1637x over previous
#include <cuda_runtime.h>
#include <math.h>
#include <stdint.h>

// Problem constants
#define BB 2
#define CC 4
#define HH 256
#define WW 256
#define FF 128
#define NPIX (HH*WW)                 // 65536
#define NTOT (BB*CC*NPIX)            // 524288
#define NHID (2*BB*FF*NPIX)          // both branches: 33554432 floats (134MB)

typedef unsigned long long u64;
typedef unsigned int u32;

// ---------------- scratch (device globals; no allocation allowed) -------------
__device__ float g_stateA[NTOT];
__device__ float g_stateB[NTOT];
__device__ float g_hid[NHID];        // hidden activations, [branch*BB+b][128][HW]
__device__ float g_upd[NTOT];
__device__ float g_nbr[NTOT];
__device__ float g_sim[NTOT];
__device__ float g_boxst[NTOT];
__device__ float g_gfeat[BB*CC];
__device__ float g_scale[BB*CC];
__device__ float g_simsum[BB*CC];
__device__ float g_loss;
__device__ unsigned g_ticket;        // last-block ticket for gfeat->scale fusion

__device__ __forceinline__ float sigm(float v) { return 1.f/(1.f+expf(-v)); }

// ---------------- f32x2 helpers -----------------------------------------------
__device__ __forceinline__ u64 pack2(float lo, float hi) {
    u64 r; asm("mov.b64 %0, {%1, %2};" : "=l"(r) : "f"(lo), "f"(hi)); return r;
}
__device__ __forceinline__ u64 dup2(float v) { return pack2(v, v); }
__device__ __forceinline__ void fma2(u64& d, u64 a, u64 b) {
    asm("fma.rn.f32x2 %0, %1, %2, %0;" : "+l"(d) : "l"(a), "l"(b));
}
__device__ __forceinline__ float lo2(u64 v) { return __uint_as_float((unsigned)(v & 0xffffffffu)); }
__device__ __forceinline__ float hi2(u64 v) { return __uint_as_float((unsigned)(v >> 32)); }

// ---------------- gfeat + scale fused (last-block pattern) --------------------
__global__ void k_gfeat_scale(const float* __restrict__ x,
                              const float* __restrict__ fc_w,
                              const float* __restrict__ fc_b,
                              const float* __restrict__ modw)
{
    __shared__ float red[256];
    __shared__ unsigned s_last;
    int bc = blockIdx.x;
    const float* p = x + (size_t)bc*NPIX;
    float s = 0.f;
    for (int i = threadIdx.x; i < NPIX; i += 256) s += p[i];
    red[threadIdx.x] = s; __syncthreads();
    for (int o = 128; o > 0; o >>= 1) { if (threadIdx.x < o) red[threadIdx.x] += red[threadIdx.x+o]; __syncthreads(); }
    if (threadIdx.x == 0) {
        g_gfeat[bc] = red[0] * (1.f/(float)NPIX);
        __threadfence();
        s_last = atomicAdd(&g_ticket, 1u);
    }
    __syncthreads();
    if (s_last == BB*CC - 1) {   // last block computes scales
        int t = threadIdx.x;
        if (t < BB*CC) {
            int b = t / CC, c = t % CC;
            float z = fc_b[c];
            #pragma unroll
            for (int j = 0; j < CC; j++) z += g_gfeat[b*CC+j] * fc_w[c*CC+j];
            g_scale[t] = sigm(z) * sigm(modw[c]);
        }
        if (t == 0) { g_loss = 0.f; g_ticket = 0u; }  // reset for next graph replay
    }
}

// ---------------- state init ---------------------------------------------------
__global__ void k_init(const float* __restrict__ x)
{
    int i = blockIdx.x*256 + threadIdx.x;
    if (i < NTOT) g_stateA[i] = x[i] * g_scale[i >> 16];
}

// ---------------- conv 4 -> 128, 3x3, BOTH branches (runtime dilation) --------
// grid (8,16,4): z = br*BB + b. S = 1+br. Tile 32x16 px, 2 px/thread.
// AT FFMA2 ROOFLINE — do not touch.
__global__ void __launch_bounds__(256) k_c2f(
    const float* __restrict__ state,
    const float* __restrict__ w_su, const float* __restrict__ b_su,
    const float* __restrict__ w_nu, const float* __restrict__ b_nu)
{
    constexpr int TW = 36, TH = 20;     // worst case halo (S=2)
    __shared__ float s_wt[36*FF];       // [j][oc] transposed
    __shared__ float s_b[FF];
    __shared__ float s_in[CC*TH*TW];
    const int tid = threadIdx.x;
    const int z = blockIdx.z;
    const int br = z >> 1, b = z & 1;
    const int S = 1 + br;
    const float* w    = br ? w_nu : w_su;
    const float* bias = br ? b_nu : b_su;
    const int x0 = blockIdx.x*32, y0 = blockIdx.y*16;

    // zero simsum once per grid (before iter_a of this iteration)
    if (blockIdx.x == 0 && blockIdx.y == 0 && z == 0 && tid < BB*CC) g_simsum[tid] = 0.f;

    for (int i = tid; i < 36*FF; i += 256) {
        int oc = i & 127, j = i >> 7;
        s_wt[i] = w[oc*36 + j];
    }
    if (tid < FF) s_b[tid] = bias[tid];
    for (int i = tid; i < CC*TH*TW; i += 256) {
        int c = i/(TH*TW), r = i%(TH*TW);
        int sy = r/TW, sx = r%TW;
        int gy = y0+sy-S, gx = x0+sx-S;
        float v = 0.f;
        if (gy >= 0 && gy < HH && gx >= 0 && gx < WW)
            v = state[((size_t)(b*CC+c) << 16) + (gy<<8) + gx];
        s_in[i] = v;
    }
    __syncthreads();

    const int tx = tid & 15, ty = tid >> 4;
    const int lx = (S == 1) ? 2*tx : ((tx & 1) + (tx >> 1)*4);
    const int gx0 = x0 + lx, gy = y0 + ty;

    u64 dup[48];
    #pragma unroll
    for (int c = 0; c < 4; c++)
        #pragma unroll
        for (int r = 0; r < 3; r++)
            #pragma unroll
            for (int k = 0; k < 4; k++)
                dup[c*12 + r*4 + k] = dup2(s_in[(c*TH + ty + r*S)*TW + lx + k*S]);

    float* outp = g_hid + ((size_t)z*FF << 16) + (gy<<8) + gx0;
    #pragma unroll 2
    for (int op = 0; op < 64; op++) {
        u64 a0 = *(const u64*)&s_b[2*op];
        u64 a1 = a0;
        #pragma unroll
        for (int c = 0; c < 4; c++)
            #pragma unroll
            for (int ky = 0; ky < 3; ky++)
                #pragma unroll
                for (int kx = 0; kx < 3; kx++) {
                    u64 w2 = *(const u64*)&s_wt[(c*9 + ky*3 + kx)*FF + 2*op];
                    fma2(a0, dup[c*12 + ky*4 + kx],     w2);
                    fma2(a1, dup[c*12 + ky*4 + kx + 1], w2);
                }
        outp[(size_t)(2*op)   << 16]       = fmaxf(lo2(a0), 0.f);
        outp[(size_t)(2*op+1) << 16]       = fmaxf(hi2(a0), 0.f);
        outp[((size_t)(2*op)   << 16) + S] = fmaxf(lo2(a1), 0.f);
        outp[((size_t)(2*op+1) << 16) + S] = fmaxf(hi2(a1), 0.f);
    }
}

// ---------------- conv 128 -> 4, 3x3 — cp.async staging + HOISTED offsets -----
// cp.async removes staging registers (R13: regs 152->50); hoisted offsets
// remove the per-chunk div/mod ALU (R13: alu=50.1%). off[23] costs ~23 regs
// on a 50-reg base — affordable now, unlike R10's 152-reg base.
template<int S>
__device__ __forceinline__ void f2c_run(
    float* s_act, float* s_w,
    const float* __restrict__ bias,
    const float* __restrict__ actbase, float* __restrict__ out,
    int b, int x0, int y0, int tid)
{
    constexpr int TW = 36, TH = 20;
    constexpr int CH = 4, NCHUNK = FF/CH;   // 32 chunks
    constexpr int NACT = CH*TH*TW;          // 2880
    constexpr int PREN = (NACT + 127)/128;  // 23
    constexpr u32 INVALID = 0xFFFFFFFFu;

    const int tx = tid & 7, ty = tid >> 3;
    const int lx = 4*tx;
    const u32 s_act_u32 = (u32)__cvta_generic_to_shared(s_act);

    // hoisted, chunk-invariant staging element-offsets (computed once)
    u32 off[PREN];
    {
        int n = 0;
        for (int i = tid; i < NACT; i += 128, n++) {
            int c = i/(TH*TW), r = i%(TH*TW), sy = r/TW, sx = r%TW;
            int gy = y0+sy-S, gx = x0+sx-S;
            bool ok = (gy >= 0 && gy < HH && gx >= 0 && gx < WW);
            off[n] = ok ? (u32)((c<<16) + (gy<<8) + gx) : INVALID;
        }
        for (; n < PREN; n++) off[n] = INVALID;
    }

    u64 a01[4], a23[4];   // per px p: (oc0,oc1) and (oc2,oc3)
    {
        u64 b01 = pack2(bias[0], bias[1]);
        u64 b23 = pack2(bias[2], bias[3]);
        #pragma unroll
        for (int p = 0; p < 4; p++) { a01[p] = b01; a23[p] = b23; }
    }

    // staging: 23 x (predicated cp.async) per chunk, offsets from registers
    auto stage = [&](u32 sbuf, const float* nb) {
        #pragma unroll
        for (int n = 0; n < PREN; n++) {
            int i = tid + n*128;
            if (i < NACT) {
                bool ok = (off[n] != INVALID);
                const float* gp = ok ? nb + off[n] : nb;
                asm volatile("cp.async.ca.shared.global [%0], [%1], 4, %2;"
                             :: "r"(sbuf + (u32)(i*4)), "l"(gp), "r"(ok ? 4 : 0)
                             : "memory");
            }
        }
        asm volatile("cp.async.commit_group;" ::: "memory");
    };

    // prologue: stage chunk 0 into buffer 0
    stage(s_act_u32, actbase);

    for (int ck = 0; ck < NCHUNK; ck++) {
        asm volatile("cp.async.wait_group 0;" ::: "memory");
        __syncthreads();
        if (ck + 1 < NCHUNK) {
            const float* nb = actbase + ((size_t)((ck+1)*CH) << 16);
            stage(s_act_u32 + (u32)(((ck+1) & 1) * NACT * 4), nb);
        }
        const float* buf = s_act + (ck & 1) * NACT;
        #pragma unroll
        for (int c = 0; c < CH; c++) {
            const int ic = ck*CH + c;
            #pragma unroll
            for (int r = 0; r < 3; r++) {
                const float* rowp = &buf[(c*TH + ty + r*S)*TW + lx];
                float4 q0 = *(const float4*)rowp;       // cols lx..lx+3
                float4 q1 = *(const float4*)(rowp + 4); // cols lx+4..lx+7
                u64 dd[8];
                dd[0] = dup2(q0.x); dd[1] = dup2(q0.y);
                dd[2] = dup2(q0.z); dd[3] = dup2(q0.w);
                dd[4] = dup2(q1.x); dd[5] = dup2(q1.y);
                dd[6] = dup2(q1.z); dd[7] = dup2(q1.w);
                #pragma unroll
                for (int k = 0; k < 3; k++) {
                    longlong2 wv = *(const longlong2*)&s_w[(ic*9 + r*3 + k)*4];
                    #pragma unroll
                    for (int p = 0; p < 4; p++) {
                        fma2(a01[p], dd[p + k*S], (u64)wv.x);
                        fma2(a23[p], dd[p + k*S], (u64)wv.y);
                    }
                }
            }
        }
    }

    const int gx0 = x0 + lx, gy = y0 + ty;
    size_t base = ((size_t)b*CC << 16) + (gy<<8) + gx0;
    float4 v0 = make_float4(lo2(a01[0]), lo2(a01[1]), lo2(a01[2]), lo2(a01[3]));
    float4 v1 = make_float4(hi2(a01[0]), hi2(a01[1]), hi2(a01[2]), hi2(a01[3]));
    float4 v2 = make_float4(lo2(a23[0]), lo2(a23[1]), lo2(a23[2]), lo2(a23[3]));
    float4 v3 = make_float4(hi2(a23[0]), hi2(a23[1]), hi2(a23[2]), hi2(a23[3]));
    *(float4*)&out[base]                     = v0;
    *(float4*)&out[base + ((size_t)1 << 16)] = v1;
    *(float4*)&out[base + ((size_t)2 << 16)] = v2;
    *(float4*)&out[base + ((size_t)3 << 16)] = v3;
}

__global__ void __launch_bounds__(128) k_f2c(
    const float* __restrict__ w_su, const float* __restrict__ b_su,
    const float* __restrict__ w_nu, const float* __restrict__ b_nu)
{
    constexpr int NACT = 4*20*36;           // 2880
    extern __shared__ float smem[];
    float* s_act = smem;                    // 2 x 2880 floats (23KB ping-pong)
    float* s_w   = smem + 2*NACT;           // 4608 floats (18KB): [ic][kj][oc]
    const int tid = threadIdx.x;
    const int z = blockIdx.z;
    const int br = z >> 1, b = z & 1;
    const float* w    = br ? w_nu : w_su;
    const float* bias = br ? b_nu : b_su;
    float* out = (br ? g_nbr : g_upd);
    const float* actbase = g_hid + ((size_t)z*FF << 16);
    const int x0 = blockIdx.x*32, y0 = blockIdx.y*16;

    for (int i = tid; i < CC*FF*9; i += 128) {
        int oc = i & 3, t = i >> 2;
        int ic = t / 9, kj = t % 9;
        s_w[i] = w[((size_t)oc*FF + ic)*9 + kj];
    }
    __syncthreads();   // weights ready before compute reads them

    if (br == 0) f2c_run<1>(s_act, s_w, bias, actbase, out, b, x0, y0, tid);
    else         f2c_run<2>(s_act, s_w, bias, actbase, out, b, x0, y0, tid);
}

// ---------------- fused gradient-magnitude + box sums + similarity ------------
__global__ void k_iter_a(const float* __restrict__ state,
                         const float* __restrict__ skx, const float* __restrict__ sky)
{
    __shared__ float s_st[22*22];
    __shared__ float s_gm[20*20];
    __shared__ float red[256];
    const int bc = blockIdx.z;
    const int c = bc & 3;
    const int x0 = blockIdx.x*16, y0 = blockIdx.y*16;
    const int tid = threadIdx.x;
    const float* sp = state + ((size_t)bc << 16);

    for (int i = tid; i < 22*22; i += 256) {
        int sy = i/22, sx = i%22;
        int gy = y0+sy-3, gx = x0+sx-3;
        float v = 0.f;
        if (gy >= 0 && gy < HH && gx >= 0 && gx < WW) v = sp[(gy<<8) + gx];
        s_st[i] = v;
    }
    float kx[9], ky[9];
    #pragma unroll
    for (int j = 0; j < 9; j++) { kx[j] = skx[c*9+j]; ky[j] = sky[c*9+j]; }
    __syncthreads();

    for (int i = tid; i < 20*20; i += 256) {
        int sy = i/20, sx = i%20;
        int gy = y0+sy-2, gx = x0+sx-2;
        float v = 0.f;
        if (gy >= 0 && gy < HH && gx >= 0 && gx < WW) {
            float ax = 0.f, ay = 0.f;
            #pragma unroll
            for (int dy = 0; dy < 3; dy++)
                #pragma unroll
                for (int dx = 0; dx < 3; dx++) {
                    float s = s_st[(sy+dy)*22 + sx+dx];
                    ax += s * kx[dy*3+dx];
                    ay += s * ky[dy*3+dx];
                }
            v = sqrtf(ax*ax + ay*ay);
        }
        s_gm[i] = v;
    }
    __syncthreads();

    const int tx = tid & 15, ty = tid >> 4;
    float g0 = s_gm[(ty+2)*20 + tx+2];
    float s1 = 0.f, s2 = 0.f, s3 = 0.f;
    #pragma unroll
    for (int dy = 0; dy < 5; dy++)
        #pragma unroll
        for (int dx = 0; dx < 5; dx++) {
            float g = s_gm[(ty+dy)*20 + tx+dx];
            s1 += g; s2 += g*g;
            s3 += s_st[(ty+1+dy)*22 + tx+1+dx];
        }
    float dist = s2 - 2.f*g0*s1 + 25.f*g0*g0;
    float sv = expf(-2.f*dist);
    size_t oi = ((size_t)bc << 16) + ((y0+ty)<<8) + (x0+tx);
    g_sim[oi]   = sv;
    g_boxst[oi] = s3;

    red[tid] = sv; __syncthreads();
    for (int o = 128; o > 0; o >>= 1) { if (tid < o) red[tid] += red[tid+o]; __syncthreads(); }
    if (tid == 0) atomicAdd(&g_simsum[bc], red[0]);
}

// ---------------- fused dynamic conv + combine (ping-pong state) --------------
__global__ void k_iter_b(const float* __restrict__ state, float* __restrict__ nstate,
                         const float* __restrict__ w, const float* __restrict__ bias)
{
    __shared__ float s_st[4*18*18];
    __shared__ float s_w[144];
    __shared__ float s_b[4];
    const int b = blockIdx.z;
    const int x0 = blockIdx.x*16, y0 = blockIdx.y*16;
    const int tid = threadIdx.x;

    if (tid < 144) s_w[tid] = w[tid];
    if (tid < 4)   s_b[tid] = bias[tid];
    for (int i = tid; i < 4*18*18; i += 256) {
        int c = i/324, r = i%324, sy = r/18, sx = r%18;
        int gy = y0+sy-1, gx = x0+sx-1;
        float v = 0.f;
        if (gy >= 0 && gy < HH && gx >= 0 && gx < WW)
            v = state[((size_t)(b*4+c) << 16) + (gy<<8) + gx];
        s_st[i] = v;
    }
    __syncthreads();

    const int tx = tid & 15, ty = tid >> 4;
    float hf[4] = { s_b[0], s_b[1], s_b[2], s_b[3] };
    #pragma unroll
    for (int ic = 0; ic < 4; ic++) {
        float v[9];
        #pragma unroll
        for (int dy = 0; dy < 3; dy++)
            #pragma unroll
            for (int dx = 0; dx < 3; dx++)
                v[dy*3+dx] = s_st[ic*324 + (ty+dy)*18 + tx+dx];
        #pragma unroll
        for (int oc = 0; oc < 4; oc++)
            #pragma unroll
            for (int j = 0; j < 9; j++)
                hf[oc] += v[j] * s_w[(oc*4+ic)*9 + j];
    }

    #pragma unroll
    for (int cc = 0; cc < 4; cc++) {
        size_t idx = ((size_t)(b*4+cc) << 16) + ((y0+ty)<<8) + (x0+tx);
        float inv = 1.f/(g_simsum[b*4+cc] + 1e-8f);
        nstate[idx] = g_sim[idx]*inv*g_boxst[idx] + g_upd[idx] + g_nbr[idx] + hf[cc];
    }
}

// ---------------- fused final: gm + hf + selection + loss ---------------------
__global__ void k_final(const float* __restrict__ state, const int* __restrict__ tgt,
                        const float* __restrict__ dw, const float* __restrict__ db,
                        const float* __restrict__ skx, const float* __restrict__ sky,
                        float* __restrict__ out)
{
    __shared__ float s_st[4*18*18];
    __shared__ float s_w[144];
    __shared__ float s_b[4];
    __shared__ float s_k[2*36];
    __shared__ float red[256];
    const int b = blockIdx.z;
    const int x0 = blockIdx.x*16, y0 = blockIdx.y*16;
    const int tid = threadIdx.x;

    if (tid < 144) s_w[tid] = dw[tid];
    if (tid < 4)   s_b[tid] = db[tid];
    if (tid < 36)  s_k[tid] = skx[tid];
    if (tid >= 36 && tid < 72) s_k[tid] = sky[tid-36];
    for (int i = tid; i < 4*18*18; i += 256) {
        int c = i/324, r = i%324, sy = r/18, sx = r%18;
        int gy = y0+sy-1, gx = x0+sx-1;
        float v = 0.f;
        if (gy >= 0 && gy < HH && gx >= 0 && gx < WW)
            v = state[((size_t)(b*4+c) << 16) + (gy<<8) + gx];
        s_st[i] = v;
    }
    __syncthreads();

    const int tx = tid & 15, ty = tid >> 4;
    const int t = tgt[b];
    float lsum = 0.f;

    float hf[4] = { s_b[0], s_b[1], s_b[2], s_b[3] };
    #pragma unroll
    for (int ic = 0; ic < 4; ic++) {
        float v[9];
        #pragma unroll
        for (int dy = 0; dy < 3; dy++)
            #pragma unroll
            for (int dx = 0; dx < 3; dx++)
                v[dy*3+dx] = s_st[ic*324 + (ty+dy)*18 + tx+dx];
        #pragma unroll
        for (int oc = 0; oc < 4; oc++)
            #pragma unroll
            for (int j = 0; j < 9; j++)
                hf[oc] += v[j] * s_w[(oc*4+ic)*9 + j];
    }

    #pragma unroll
    for (int c = 0; c < 4; c++) {
        float ax = 0.f, ay = 0.f;
        #pragma unroll
        for (int dy = 0; dy < 3; dy++)
            #pragma unroll
            for (int dx = 0; dx < 3; dx++) {
                float s = s_st[c*324 + (ty+dy)*18 + tx+dx];
                ax += s * s_k[c*9 + dy*3+dx];
                ay += s * s_k[36 + c*9 + dy*3+dx];
            }
        float gmv = sqrtf(ax*ax + ay*ay);
        float hfs = sigm(hf[c]);
        float sg  = sigm(gmv);
        float pos, neg;
        if      (t == 0) { pos = hfs;     neg = 1.f - sg;      }
        else if (t == 1) { pos = sg;      neg = 1.f - hfs;     }
        else if (t == 2) { pos = hfs*sg;  neg = 1.f - hfs*sg;  }
        else             { float q = sigm(gmv*hfs); pos = q; neg = 1.f - q; }
        pos = fminf(fmaxf(pos, 0.f), 1.f);
        neg = fminf(fmaxf(neg, 0.f), 1.f);
        float ep = expf(pos), en = expf(neg);
        float sel = ep / (ep + en + 1e-8f);
        size_t idx = ((size_t)(b*4+c) << 16) + ((y0+ty)<<8) + (x0+tx);
        out[idx] = state[idx] * sel;
        lsum += sel*neg + (1.f - sel)*pos;
    }

    red[tid] = lsum; __syncthreads();
    for (int o = 128; o > 0; o >>= 1) { if (tid < o) red[tid] += red[tid+o]; __syncthreads(); }
    if (tid == 0) atomicAdd(&g_loss, red[0]);
}

__global__ void k_write_loss(float* __restrict__ out)
{
    if (threadIdx.x == 0) out[NTOT] = g_loss * (1.f/(float)NTOT);
}

// ---------------- launcher -----------------------------------------------------
extern "C" void kernel_launch(void* const* d_in, const int* in_sizes, int n_in,
                              void* d_out, int out_size)
{
    const float* x      = (const float*)d_in[0];
    const int*   tgt    = (const int*)  d_in[1];
    const float* fc_w   = (const float*)d_in[2];
    const float* fc_b   = (const float*)d_in[3];
    const float* modw   = (const float*)d_in[4];
    const float* su_w1  = (const float*)d_in[5];
    const float* su_b1  = (const float*)d_in[6];
    const float* su_w2  = (const float*)d_in[7];
    const float* su_b2  = (const float*)d_in[8];
    const float* nu_w1  = (const float*)d_in[9];
    const float* nu_b1  = (const float*)d_in[10];
    const float* nu_w2  = (const float*)d_in[11];
    const float* nu_b2  = (const float*)d_in[12];
    const float* dc_w   = (const float*)d_in[13];
    const float* dc_b   = (const float*)d_in[14];
    const float* sob_kx = (const float*)d_in[15];
    const float* sob_ky = (const float*)d_in[16];
    float* out = (float*)d_out;

    float *pA, *pB;
    cudaGetSymbolAddress((void**)&pA, g_stateA);
    cudaGetSymbolAddress((void**)&pB, g_stateB);

    // dynamic smem for f2c: 2*2880 + 4608 floats = 41472 B
    const int smemF = (2*2880 + 4608)*4;
    cudaFuncSetAttribute(k_f2c, cudaFuncAttributeMaxDynamicSharedMemorySize, smemF);

    const dim3 cgrid(8, 16, 4);        // conv tiles 32x16, z = branch*BB+b
    const dim3 agrid(16, 16, BB*CC);   // iter_a tiles 16x16 per (b,c)
    const dim3 bgrid(16, 16, BB);      // iter_b / final tiles 16x16 per b
    const int PW = (NTOT + 255)/256;

    k_gfeat_scale<<<BB*CC, 256>>>(x, fc_w, fc_b, modw);
    k_init<<<PW, 256>>>(x);

    float* cur = pA;
    float* nxt = pB;
    for (int it = 0; it < 3; it++) {
        k_c2f<<<cgrid, 256>>>(cur, su_w1, su_b1, nu_w1, nu_b1);
        k_f2c<<<cgrid, 128, smemF>>>(su_w2, su_b2, nu_w2, nu_b2);
        k_iter_a<<<agrid, 256>>>(cur, sob_kx, sob_ky);
        k_iter_b<<<bgrid, 256>>>(cur, nxt, dc_w, dc_b);
        float* tmpp = cur; cur = nxt; nxt = tmpp;
    }

    k_final<<<bgrid, 256>>>(cur, tgt, dc_w, dc_b, sob_kx, sob_ky, out);
    if (out_size > NTOT) k_write_loss<<<1, 32>>>(out);
}

// round 15
// speedup vs baseline: 1.3185x; 1.1330x over previous
#include <cuda_runtime.h>
#include <math.h>
#include <stdint.h>

// Problem constants
#define BB 2
#define CC 4
#define HH 256
#define WW 256
#define FF 128
#define NPIX (HH*WW)                 // 65536
#define NTOT (BB*CC*NPIX)            // 524288
#define NHID (2*BB*FF*NPIX)          // both branches: 33554432 floats (134MB)

typedef unsigned long long u64;
typedef unsigned int u32;

// ---------------- scratch (device globals; no allocation allowed) -------------
__device__ float g_stateA[NTOT];
__device__ float g_stateB[NTOT];
__device__ float g_hid[NHID];        // hidden activations, [branch*BB+b][128][HW]
__device__ float g_upd[NTOT];
__device__ float g_upd2[NTOT];
__device__ float g_nbr[NTOT];
__device__ float g_nbr2[NTOT];
__device__ float g_sim[NTOT];
__device__ float g_boxst[NTOT];
__device__ float g_gfeat[BB*CC];
__device__ float g_scale[BB*CC];
__device__ float g_simsum[BB*CC];
__device__ float g_loss;
__device__ unsigned g_ticket;        // last-block ticket for gfeat->scale fusion

__device__ __forceinline__ float sigm(float v) { return 1.f/(1.f+expf(-v)); }

// ---------------- f32x2 helpers -----------------------------------------------
__device__ __forceinline__ u64 pack2(float lo, float hi) {
    u64 r; asm("mov.b64 %0, {%1, %2};" : "=l"(r) : "f"(lo), "f"(hi)); return r;
}
__device__ __forceinline__ u64 dup2(float v) { return pack2(v, v); }
__device__ __forceinline__ void fma2(u64& d, u64 a, u64 b) {
    asm("fma.rn.f32x2 %0, %1, %2, %0;" : "+l"(d) : "l"(a), "l"(b));
}
__device__ __forceinline__ float lo2(u64 v) { return __uint_as_float((unsigned)(v & 0xffffffffu)); }
__device__ __forceinline__ float hi2(u64 v) { return __uint_as_float((unsigned)(v >> 32)); }

// ---------------- gfeat + scale fused (last-block pattern) --------------------
__global__ void k_gfeat_scale(const float* __restrict__ x,
                              const float* __restrict__ fc_w,
                              const float* __restrict__ fc_b,
                              const float* __restrict__ modw)
{
    __shared__ float red[256];
    __shared__ unsigned s_last;
    int bc = blockIdx.x;
    const float* p = x + (size_t)bc*NPIX;
    float s = 0.f;
    for (int i = threadIdx.x; i < NPIX; i += 256) s += p[i];
    red[threadIdx.x] = s; __syncthreads();
    for (int o = 128; o > 0; o >>= 1) { if (threadIdx.x < o) red[threadIdx.x] += red[threadIdx.x+o]; __syncthreads(); }
    if (threadIdx.x == 0) {
        g_gfeat[bc] = red[0] * (1.f/(float)NPIX);
        __threadfence();
        s_last = atomicAdd(&g_ticket, 1u);
    }
    __syncthreads();
    if (s_last == BB*CC - 1) {   // last block computes scales
        int t = threadIdx.x;
        if (t < BB*CC) {
            int b = t / CC, c = t % CC;
            float z = fc_b[c];
            #pragma unroll
            for (int j = 0; j < CC; j++) z += g_gfeat[b*CC+j] * fc_w[c*CC+j];
            g_scale[t] = sigm(z) * sigm(modw[c]);
        }
        if (t == 0) { g_loss = 0.f; g_ticket = 0u; }  // reset for next graph replay
    }
}

// ---------------- state init ---------------------------------------------------
__global__ void k_init(const float* __restrict__ x)
{
    int i = blockIdx.x*256 + threadIdx.x;
    if (i < NTOT) g_stateA[i] = x[i] * g_scale[i >> 16];
}

// ---------------- conv 4 -> 128, 3x3, BOTH branches (runtime dilation) --------
// grid (8,16,4): z = br*BB + b. S = 1+br. Tile 32x16 px, 2 px/thread.
__global__ void __launch_bounds__(256) k_c2f(
    const float* __restrict__ state,
    const float* __restrict__ w_su, const float* __restrict__ b_su,
    const float* __restrict__ w_nu, const float* __restrict__ b_nu)
{
    constexpr int TW = 36, TH = 20;     // worst case halo (S=2)
    __shared__ float s_wt[36*FF];       // [j][oc] transposed
    __shared__ float s_b[FF];
    __shared__ float s_in[CC*TH*TW];
    const int tid = threadIdx.x;
    const int z = blockIdx.z;
    const int br = z >> 1, b = z & 1;
    const int S = 1 + br;
    const float* w    = br ? w_nu : w_su;
    const float* bias = br ? b_nu : b_su;
    const int x0 = blockIdx.x*32, y0 = blockIdx.y*16;

    // zero simsum once per grid (before iter_a of this iteration)
    if (blockIdx.x == 0 && blockIdx.y == 0 && z == 0 && tid < BB*CC) g_simsum[tid] = 0.f;

    for (int i = tid; i < 36*FF; i += 256) {
        int oc = i & 127, j = i >> 7;
        s_wt[i] = w[oc*36 + j];
    }
    if (tid < FF) s_b[tid] = bias[tid];
    for (int i = tid; i < CC*TH*TW; i += 256) {
        int c = i/(TH*TW), r = i%(TH*TW);
        int sy = r/TW, sx = r%TW;
        int gy = y0+sy-S, gx = x0+sx-S;
        float v = 0.f;
        if (gy >= 0 && gy < HH && gx >= 0 && gx < WW)
            v = state[((size_t)(b*CC+c) << 16) + (gy<<8) + gx];
        s_in[i] = v;
    }
    __syncthreads();

    const int tx = tid & 15, ty = tid >> 4;
    const int lx = (S == 1) ? 2*tx : ((tx & 1) + (tx >> 1)*4);
    const int gx0 = x0 + lx, gy = y0 + ty;

    u64 dup[48];
    #pragma unroll
    for (int c = 0; c < 4; c++)
        #pragma unroll
        for (int r = 0; r < 3; r++)
            #pragma unroll
            for (int k = 0; k < 4; k++)
                dup[c*12 + r*4 + k] = dup2(s_in[(c*TH + ty + r*S)*TW + lx + k*S]);

    float* outp = g_hid + ((size_t)z*FF << 16) + (gy<<8) + gx0;
    #pragma unroll 2
    for (int op = 0; op < 64; op++) {
        u64 a0 = *(const u64*)&s_b[2*op];
        u64 a1 = a0;
        #pragma unroll
        for (int c = 0; c < 4; c++)
            #pragma unroll
            for (int ky = 0; ky < 3; ky++)
                #pragma unroll
                for (int kx = 0; kx < 3; kx++) {
                    u64 w2 = *(const u64*)&s_wt[(c*9 + ky*3 + kx)*FF + 2*op];
                    fma2(a0, dup[c*12 + ky*4 + kx],     w2);
                    fma2(a1, dup[c*12 + ky*4 + kx + 1], w2);
                }
        outp[(size_t)(2*op)   << 16]       = fmaxf(lo2(a0), 0.f);
        outp[(size_t)(2*op+1) << 16]       = fmaxf(hi2(a0), 0.f);
        outp[((size_t)(2*op)   << 16) + S] = fmaxf(lo2(a1), 0.f);
        outp[((size_t)(2*op+1) << 16) + S] = fmaxf(hi2(a1), 0.f);
    }
}

// ---------------- conv 128 -> 4, split over ic halves (K-split) ---------------
// grid (8,16,8): z = kh*4 + br*2 + b. Each block contracts 64 ic.
// cp.async staging + hoisted offsets (R14 proven inner loop, KH=64 chunks=16).
template<int S>
__device__ __forceinline__ void f2c_run(
    float* s_act, float* s_w,
    float bias0, float bias1, float bias2, float bias3,
    const float* __restrict__ actbase, float* __restrict__ out,
    int b, int x0, int y0, int tid)
{
    constexpr int TW = 36, TH = 20;
    constexpr int CH = 4, NCHUNK = 64/CH;   // 16 chunks (64 ic per block)
    constexpr int NACT = CH*TH*TW;          // 2880
    constexpr int PREN = (NACT + 127)/128;  // 23
    constexpr u32 INVALID = 0xFFFFFFFFu;

    const int tx = tid & 7, ty = tid >> 3;
    const int lx = 4*tx;
    const u32 s_act_u32 = (u32)__cvta_generic_to_shared(s_act);

    // hoisted, chunk-invariant staging element-offsets (computed once)
    u32 off[PREN];
    {
        int n = 0;
        for (int i = tid; i < NACT; i += 128, n++) {
            int c = i/(TH*TW), r = i%(TH*TW), sy = r/TW, sx = r%TW;
            int gy = y0+sy-S, gx = x0+sx-S;
            bool ok = (gy >= 0 && gy < HH && gx >= 0 && gx < WW);
            off[n] = ok ? (u32)((c<<16) + (gy<<8) + gx) : INVALID;
        }
        for (; n < PREN; n++) off[n] = INVALID;
    }

    u64 a01[4], a23[4];   // per px p: (oc0,oc1) and (oc2,oc3)
    {
        u64 b01 = pack2(bias0, bias1);
        u64 b23 = pack2(bias2, bias3);
        #pragma unroll
        for (int p = 0; p < 4; p++) { a01[p] = b01; a23[p] = b23; }
    }

    auto stage = [&](u32 sbuf, const float* nb) {
        #pragma unroll
        for (int n = 0; n < PREN; n++) {
            int i = tid + n*128;
            if (i < NACT) {
                bool ok = (off[n] != INVALID);
                const float* gp = ok ? nb + off[n] : nb;
                asm volatile("cp.async.ca.shared.global [%0], [%1], 4, %2;"
                             :: "r"(sbuf + (u32)(i*4)), "l"(gp), "r"(ok ? 4 : 0)
                             : "memory");
            }
        }
        asm volatile("cp.async.commit_group;" ::: "memory");
    };

    // prologue: stage chunk 0 into buffer 0
    stage(s_act_u32, actbase);

    for (int ck = 0; ck < NCHUNK; ck++) {
        asm volatile("cp.async.wait_group 0;" ::: "memory");
        __syncthreads();
        if (ck + 1 < NCHUNK) {
            const float* nb = actbase + ((size_t)((ck+1)*CH) << 16);
            stage(s_act_u32 + (u32)(((ck+1) & 1) * NACT * 4), nb);
        }
        const float* buf = s_act + (ck & 1) * NACT;
        #pragma unroll
        for (int c = 0; c < CH; c++) {
            const int icl = ck*CH + c;   // local ic index 0..63 into s_w
            #pragma unroll
            for (int r = 0; r < 3; r++) {
                const float* rowp = &buf[(c*TH + ty + r*S)*TW + lx];
                float4 q0 = *(const float4*)rowp;       // cols lx..lx+3
                float4 q1 = *(const float4*)(rowp + 4); // cols lx+4..lx+7
                u64 dd[8];
                dd[0] = dup2(q0.x); dd[1] = dup2(q0.y);
                dd[2] = dup2(q0.z); dd[3] = dup2(q0.w);
                dd[4] = dup2(q1.x); dd[5] = dup2(q1.y);
                dd[6] = dup2(q1.z); dd[7] = dup2(q1.w);
                #pragma unroll
                for (int k = 0; k < 3; k++) {
                    longlong2 wv = *(const longlong2*)&s_w[(icl*9 + r*3 + k)*4];
                    #pragma unroll
                    for (int p = 0; p < 4; p++) {
                        fma2(a01[p], dd[p + k*S], (u64)wv.x);
                        fma2(a23[p], dd[p + k*S], (u64)wv.y);
                    }
                }
            }
        }
    }

    const int gx0 = x0 + lx, gy = y0 + ty;
    size_t base = ((size_t)b*CC << 16) + (gy<<8) + gx0;
    float4 v0 = make_float4(lo2(a01[0]), lo2(a01[1]), lo2(a01[2]), lo2(a01[3]));
    float4 v1 = make_float4(hi2(a01[0]), hi2(a01[1]), hi2(a01[2]), hi2(a01[3]));
    float4 v2 = make_float4(lo2(a23[0]), lo2(a23[1]), lo2(a23[2]), lo2(a23[3]));
    float4 v3 = make_float4(hi2(a23[0]), hi2(a23[1]), hi2(a23[2]), hi2(a23[3]));
    *(float4*)&out[base]                     = v0;
    *(float4*)&out[base + ((size_t)1 << 16)] = v1;
    *(float4*)&out[base + ((size_t)2 << 16)] = v2;
    *(float4*)&out[base + ((size_t)3 << 16)] = v3;
}

__global__ void __launch_bounds__(128) k_f2c(
    const float* __restrict__ w_su, const float* __restrict__ b_su,
    const float* __restrict__ w_nu, const float* __restrict__ b_nu)
{
    constexpr int NACT = 4*20*36;           // 2880
    extern __shared__ float smem[];
    float* s_act = smem;                    // 2 x 2880 floats (23KB ping-pong)
    float* s_w   = smem + 2*NACT;           // 64*9*4 = 2304 floats (9KB)
    const int tid = threadIdx.x;
    const int z = blockIdx.z;
    const int kh = z >> 2;                  // ic half: 0 or 1
    const int br = (z >> 1) & 1, b = z & 1;
    const int icbase = kh * 64;
    const float* w    = br ? w_nu : w_su;
    const float* bias = br ? b_nu : b_su;
    float* out = kh ? (br ? g_nbr2 : g_upd2) : (br ? g_nbr : g_upd);
    const float* actbase = g_hid + ((size_t)(br*BB+b)*FF << 16) + ((size_t)icbase << 16);
    const int x0 = blockIdx.x*32, y0 = blockIdx.y*16;

    // weights for this ic half: [icl][kj][oc], icl = 0..63
    for (int i = tid; i < CC*64*9; i += 128) {
        int oc = i & 3, t = i >> 2;
        int icl = t / 9, kj = t % 9;
        s_w[i] = w[((size_t)oc*FF + icbase + icl)*9 + kj];
    }
    __syncthreads();   // weights ready before compute reads them

    float b0 = kh ? 0.f : bias[0];
    float b1 = kh ? 0.f : bias[1];
    float b2 = kh ? 0.f : bias[2];
    float b3 = kh ? 0.f : bias[3];

    if (br == 0) f2c_run<1>(s_act, s_w, b0, b1, b2, b3, actbase, out, b, x0, y0, tid);
    else         f2c_run<2>(s_act, s_w, b0, b1, b2, b3, actbase, out, b, x0, y0, tid);
}

// ---------------- fused gradient-magnitude + box sums + similarity ------------
__global__ void k_iter_a(const float* __restrict__ state,
                         const float* __restrict__ skx, const float* __restrict__ sky)
{
    __shared__ float s_st[22*22];
    __shared__ float s_gm[20*20];
    __shared__ float red[256];
    const int bc = blockIdx.z;
    const int c = bc & 3;
    const int x0 = blockIdx.x*16, y0 = blockIdx.y*16;
    const int tid = threadIdx.x;
    const float* sp = state + ((size_t)bc << 16);

    for (int i = tid; i < 22*22; i += 256) {
        int sy = i/22, sx = i%22;
        int gy = y0+sy-3, gx = x0+sx-3;
        float v = 0.f;
        if (gy >= 0 && gy < HH && gx >= 0 && gx < WW) v = sp[(gy<<8) + gx];
        s_st[i] = v;
    }
    float kx[9], ky[9];
    #pragma unroll
    for (int j = 0; j < 9; j++) { kx[j] = skx[c*9+j]; ky[j] = sky[c*9+j]; }
    __syncthreads();

    for (int i = tid; i < 20*20; i += 256) {
        int sy = i/20, sx = i%20;
        int gy = y0+sy-2, gx = x0+sx-2;
        float v = 0.f;
        if (gy >= 0 && gy < HH && gx >= 0 && gx < WW) {
            float ax = 0.f, ay = 0.f;
            #pragma unroll
            for (int dy = 0; dy < 3; dy++)
                #pragma unroll
                for (int dx = 0; dx < 3; dx++) {
                    float s = s_st[(sy+dy)*22 + sx+dx];
                    ax += s * kx[dy*3+dx];
                    ay += s * ky[dy*3+dx];
                }
            v = sqrtf(ax*ax + ay*ay);
        }
        s_gm[i] = v;
    }
    __syncthreads();

    const int tx = tid & 15, ty = tid >> 4;
    float g0 = s_gm[(ty+2)*20 + tx+2];
    float s1 = 0.f, s2 = 0.f, s3 = 0.f;
    #pragma unroll
    for (int dy = 0; dy < 5; dy++)
        #pragma unroll
        for (int dx = 0; dx < 5; dx++) {
            float g = s_gm[(ty+dy)*20 + tx+dx];
            s1 += g; s2 += g*g;
            s3 += s_st[(ty+1+dy)*22 + tx+1+dx];
        }
    float dist = s2 - 2.f*g0*s1 + 25.f*g0*g0;
    float sv = expf(-2.f*dist);
    size_t oi = ((size_t)bc << 16) + ((y0+ty)<<8) + (x0+tx);
    g_sim[oi]   = sv;
    g_boxst[oi] = s3;

    red[tid] = sv; __syncthreads();
    for (int o = 128; o > 0; o >>= 1) { if (tid < o) red[tid] += red[tid+o]; __syncthreads(); }
    if (tid == 0) atomicAdd(&g_simsum[bc], red[0]);
}

// ---------------- fused dynamic conv + combine (ping-pong state) --------------
__global__ void k_iter_b(const float* __restrict__ state, float* __restrict__ nstate,
                         const float* __restrict__ w, const float* __restrict__ bias)
{
    __shared__ float s_st[4*18*18];
    __shared__ float s_w[144];
    __shared__ float s_b[4];
    const int b = blockIdx.z;
    const int x0 = blockIdx.x*16, y0 = blockIdx.y*16;
    const int tid = threadIdx.x;

    if (tid < 144) s_w[tid] = w[tid];
    if (tid < 4)   s_b[tid] = bias[tid];
    for (int i = tid; i < 4*18*18; i += 256) {
        int c = i/324, r = i%324, sy = r/18, sx = r%18;
        int gy = y0+sy-1, gx = x0+sx-1;
        float v = 0.f;
        if (gy >= 0 && gy < HH && gx >= 0 && gx < WW)
            v = state[((size_t)(b*4+c) << 16) + (gy<<8) + gx];
        s_st[i] = v;
    }
    __syncthreads();

    const int tx = tid & 15, ty = tid >> 4;
    float hf[4] = { s_b[0], s_b[1], s_b[2], s_b[3] };
    #pragma unroll
    for (int ic = 0; ic < 4; ic++) {
        float v[9];
        #pragma unroll
        for (int dy = 0; dy < 3; dy++)
            #pragma unroll
            for (int dx = 0; dx < 3; dx++)
                v[dy*3+dx] = s_st[ic*324 + (ty+dy)*18 + tx+dx];
        #pragma unroll
        for (int oc = 0; oc < 4; oc++)
            #pragma unroll
            for (int j = 0; j < 9; j++)
                hf[oc] += v[j] * s_w[(oc*4+ic)*9 + j];
    }

    #pragma unroll
    for (int cc = 0; cc < 4; cc++) {
        size_t idx = ((size_t)(b*4+cc) << 16) + ((y0+ty)<<8) + (x0+tx);
        float inv = 1.f/(g_simsum[b*4+cc] + 1e-8f);
        nstate[idx] = g_sim[idx]*inv*g_boxst[idx]
                    + (g_upd[idx] + g_upd2[idx])
                    + (g_nbr[idx] + g_nbr2[idx]) + hf[cc];
    }
}

// ---------------- fused final: gm + hf + selection + loss ---------------------
__global__ void k_final(const float* __restrict__ state, const int* __restrict__ tgt,
                        const float* __restrict__ dw, const float* __restrict__ db,
                        const float* __restrict__ skx, const float* __restrict__ sky,
                        float* __restrict__ out)
{
    __shared__ float s_st[4*18*18];
    __shared__ float s_w[144];
    __shared__ float s_b[4];
    __shared__ float s_k[2*36];
    __shared__ float red[256];
    const int b = blockIdx.z;
    const int x0 = blockIdx.x*16, y0 = blockIdx.y*16;
    const int tid = threadIdx.x;

    if (tid < 144) s_w[tid] = dw[tid];
    if (tid < 4)   s_b[tid] = db[tid];
    if (tid < 36)  s_k[tid] = skx[tid];
    if (tid >= 36 && tid < 72) s_k[tid] = sky[tid-36];
    for (int i = tid; i < 4*18*18; i += 256) {
        int c = i/324, r = i%324, sy = r/18, sx = r%18;
        int gy = y0+sy-1, gx = x0+sx-1;
        float v = 0.f;
        if (gy >= 0 && gy < HH && gx >= 0 && gx < WW)
            v = state[((size_t)(b*4+c) << 16) + (gy<<8) + gx];
        s_st[i] = v;
    }
    __syncthreads();

    const int tx = tid & 15, ty = tid >> 4;
    const int t = tgt[b];
    float lsum = 0.f;

    float hf[4] = { s_b[0], s_b[1], s_b[2], s_b[3] };
    #pragma unroll
    for (int ic = 0; ic < 4; ic++) {
        float v[9];
        #pragma unroll
        for (int dy = 0; dy < 3; dy++)
            #pragma unroll
            for (int dx = 0; dx < 3; dx++)
                v[dy*3+dx] = s_st[ic*324 + (ty+dy)*18 + tx+dx];
        #pragma unroll
        for (int oc = 0; oc < 4; oc++)
            #pragma unroll
            for (int j = 0; j < 9; j++)
                hf[oc] += v[j] * s_w[(oc*4+ic)*9 + j];
    }

    #pragma unroll
    for (int c = 0; c < 4; c++) {
        float ax = 0.f, ay = 0.f;
        #pragma unroll
        for (int dy = 0; dy < 3; dy++)
            #pragma unroll
            for (int dx = 0; dx < 3; dx++) {
                float s = s_st[c*324 + (ty+dy)*18 + tx+dx];
                ax += s * s_k[c*9 + dy*3+dx];
                ay += s * s_k[36 + c*9 + dy*3+dx];
            }
        float gmv = sqrtf(ax*ax + ay*ay);
        float hfs = sigm(hf[c]);
        float sg  = sigm(gmv);
        float pos, neg;
        if      (t == 0) { pos = hfs;     neg = 1.f - sg;      }
        else if (t == 1) { pos = sg;      neg = 1.f - hfs;     }
        else if (t == 2) { pos = hfs*sg;  neg = 1.f - hfs*sg;  }
        else             { float q = sigm(gmv*hfs); pos = q; neg = 1.f - q; }
        pos = fminf(fmaxf(pos, 0.f), 1.f);
        neg = fminf(fmaxf(neg, 0.f), 1.f);
        float ep = expf(pos), en = expf(neg);
        float sel = ep / (ep + en + 1e-8f);
        size_t idx = ((size_t)(b*4+c) << 16) + ((y0+ty)<<8) + (x0+tx);
        out[idx] = state[idx] * sel;
        lsum += sel*neg + (1.f - sel)*pos;
    }

    red[tid] = lsum; __syncthreads();
    for (int o = 128; o > 0; o >>= 1) { if (tid < o) red[tid] += red[tid+o]; __syncthreads(); }
    if (tid == 0) atomicAdd(&g_loss, red[0]);
}

__global__ void k_write_loss(float* __restrict__ out)
{
    if (threadIdx.x == 0) out[NTOT] = g_loss * (1.f/(float)NTOT);
}

// ---------------- launcher -----------------------------------------------------
extern "C" void kernel_launch(void* const* d_in, const int* in_sizes, int n_in,
                              void* d_out, int out_size)
{
    const float* x      = (const float*)d_in[0];
    const int*   tgt    = (const int*)  d_in[1];
    const float* fc_w   = (const float*)d_in[2];
    const float* fc_b   = (const float*)d_in[3];
    const float* modw   = (const float*)d_in[4];
    const float* su_w1  = (const float*)d_in[5];
    const float* su_b1  = (const float*)d_in[6];
    const float* su_w2  = (const float*)d_in[7];
    const float* su_b2  = (const float*)d_in[8];
    const float* nu_w1  = (const float*)d_in[9];
    const float* nu_b1  = (const float*)d_in[10];
    const float* nu_w2  = (const float*)d_in[11];
    const float* nu_b2  = (const float*)d_in[12];
    const float* dc_w   = (const float*)d_in[13];
    const float* dc_b   = (const float*)d_in[14];
    const float* sob_kx = (const float*)d_in[15];
    const float* sob_ky = (const float*)d_in[16];
    float* out = (float*)d_out;

    float *pA, *pB;
    cudaGetSymbolAddress((void**)&pA, g_stateA);
    cudaGetSymbolAddress((void**)&pB, g_stateB);

    // dynamic smem for f2c: 2*2880 + 2304 floats = 32256 B
    const int smemF = (2*2880 + 2304)*4;
    cudaFuncSetAttribute(k_f2c, cudaFuncAttributeMaxDynamicSharedMemorySize, smemF);

    const dim3 cgrid(8, 16, 4);        // c2f tiles 32x16, z = branch*BB+b
    const dim3 fgrid(8, 16, 8);        // f2c K-split: z = kh*4 + branch*2 + b
    const dim3 agrid(16, 16, BB*CC);   // iter_a tiles 16x16 per (b,c)
    const dim3 bgrid(16, 16, BB);      // iter_b / final tiles 16x16 per b
    const int PW = (NTOT + 255)/256;

    k_gfeat_scale<<<BB*CC, 256>>>(x, fc_w, fc_b, modw);
    k_init<<<PW, 256>>>(x);

    float* cur = pA;
    float* nxt = pB;
    for (int it = 0; it < 3; it++) {
        k_c2f<<<cgrid, 256>>>(cur, su_w1, su_b1, nu_w1, nu_b1);
        k_f2c<<<fgrid, 128, smemF>>>(su_w2, su_b2, nu_w2, nu_b2);
        k_iter_a<<<agrid, 256>>>(cur, sob_kx, sob_ky);
        k_iter_b<<<bgrid, 256>>>(cur, nxt, dc_w, dc_b);
        float* tmpp = cur; cur = nxt; nxt = tmpp;
    }

    k_final<<<bgrid, 256>>>(cur, tgt, dc_w, dc_b, sob_kx, sob_ky, out);
    if (out_size > NTOT) k_write_loss<<<1, 32>>>(out);
}

// round 16
// speedup vs baseline: 1.3327x; 1.0108x over previous
#include <cuda_runtime.h>
#include <math.h>
#include <stdint.h>

// Problem constants
#define BB 2
#define CC 4
#define HH 256
#define WW 256
#define FF 128
#define NPIX (HH*WW)                 // 65536
#define NTOT (BB*CC*NPIX)            // 524288
#define NHID (2*BB*FF*NPIX)          // both branches: 33554432 floats (134MB)

typedef unsigned long long u64;
typedef unsigned int u32;

// ---------------- scratch (device globals; no allocation allowed) -------------
__device__ float g_stateA[NTOT];
__device__ float g_stateB[NTOT];
__device__ float g_hid[NHID];        // hidden activations, [branch*BB+b][128][HW]
__device__ float g_updq[4][NTOT];    // K-quarter partials, su branch
__device__ float g_nbrq[4][NTOT];    // K-quarter partials, nu branch
__device__ float g_sim[NTOT];
__device__ float g_boxst[NTOT];
__device__ float g_gfeat[BB*CC];
__device__ float g_scale[BB*CC];
__device__ float g_simsum[BB*CC];
__device__ float g_loss;
__device__ unsigned g_ticket;        // last-block ticket for gfeat->scale fusion

__device__ __forceinline__ float sigm(float v) { return 1.f/(1.f+expf(-v)); }

// ---------------- f32x2 helpers -----------------------------------------------
__device__ __forceinline__ u64 pack2(float lo, float hi) {
    u64 r; asm("mov.b64 %0, {%1, %2};" : "=l"(r) : "f"(lo), "f"(hi)); return r;
}
__device__ __forceinline__ u64 dup2(float v) { return pack2(v, v); }
__device__ __forceinline__ void fma2(u64& d, u64 a, u64 b) {
    asm("fma.rn.f32x2 %0, %1, %2, %0;" : "+l"(d) : "l"(a), "l"(b));
}
__device__ __forceinline__ float lo2(u64 v) { return __uint_as_float((unsigned)(v & 0xffffffffu)); }
__device__ __forceinline__ float hi2(u64 v) { return __uint_as_float((unsigned)(v >> 32)); }

// ---------------- gfeat + scale fused (last-block pattern) --------------------
__global__ void k_gfeat_scale(const float* __restrict__ x,
                              const float* __restrict__ fc_w,
                              const float* __restrict__ fc_b,
                              const float* __restrict__ modw)
{
    __shared__ float red[256];
    __shared__ unsigned s_last;
    int bc = blockIdx.x;
    const float* p = x + (size_t)bc*NPIX;
    float s = 0.f;
    for (int i = threadIdx.x; i < NPIX; i += 256) s += p[i];
    red[threadIdx.x] = s; __syncthreads();
    for (int o = 128; o > 0; o >>= 1) { if (threadIdx.x < o) red[threadIdx.x] += red[threadIdx.x+o]; __syncthreads(); }
    if (threadIdx.x == 0) {
        g_gfeat[bc] = red[0] * (1.f/(float)NPIX);
        __threadfence();
        s_last = atomicAdd(&g_ticket, 1u);
    }
    __syncthreads();
    if (s_last == BB*CC - 1) {   // last block computes scales
        int t = threadIdx.x;
        if (t < BB*CC) {
            int b = t / CC, c = t % CC;
            float z = fc_b[c];
            #pragma unroll
            for (int j = 0; j < CC; j++) z += g_gfeat[b*CC+j] * fc_w[c*CC+j];
            g_scale[t] = sigm(z) * sigm(modw[c]);
        }
        if (t == 0) { g_loss = 0.f; g_ticket = 0u; }  // reset for next graph replay
    }
}

// ---------------- state init ---------------------------------------------------
__global__ void k_init(const float* __restrict__ x)
{
    int i = blockIdx.x*256 + threadIdx.x;
    if (i < NTOT) g_stateA[i] = x[i] * g_scale[i >> 16];
}

// ---------------- conv 4 -> 128, 3x3, BOTH branches (runtime dilation) --------
// grid (8,16,4): z = br*BB + b. S = 1+br. Tile 32x16 px, 2 px/thread.
// AT FFMA2 ROOFLINE — do not touch.
__global__ void __launch_bounds__(256) k_c2f(
    const float* __restrict__ state,
    const float* __restrict__ w_su, const float* __restrict__ b_su,
    const float* __restrict__ w_nu, const float* __restrict__ b_nu)
{
    constexpr int TW = 36, TH = 20;     // worst case halo (S=2)
    __shared__ float s_wt[36*FF];       // [j][oc] transposed
    __shared__ float s_b[FF];
    __shared__ float s_in[CC*TH*TW];
    const int tid = threadIdx.x;
    const int z = blockIdx.z;
    const int br = z >> 1, b = z & 1;
    const int S = 1 + br;
    const float* w    = br ? w_nu : w_su;
    const float* bias = br ? b_nu : b_su;
    const int x0 = blockIdx.x*32, y0 = blockIdx.y*16;

    // zero simsum once per grid (before iter_a of this iteration)
    if (blockIdx.x == 0 && blockIdx.y == 0 && z == 0 && tid < BB*CC) g_simsum[tid] = 0.f;

    for (int i = tid; i < 36*FF; i += 256) {
        int oc = i & 127, j = i >> 7;
        s_wt[i] = w[oc*36 + j];
    }
    if (tid < FF) s_b[tid] = bias[tid];
    for (int i = tid; i < CC*TH*TW; i += 256) {
        int c = i/(TH*TW), r = i%(TH*TW);
        int sy = r/TW, sx = r%TW;
        int gy = y0+sy-S, gx = x0+sx-S;
        float v = 0.f;
        if (gy >= 0 && gy < HH && gx >= 0 && gx < WW)
            v = state[((size_t)(b*CC+c) << 16) + (gy<<8) + gx];
        s_in[i] = v;
    }
    __syncthreads();

    const int tx = tid & 15, ty = tid >> 4;
    const int lx = (S == 1) ? 2*tx : ((tx & 1) + (tx >> 1)*4);
    const int gx0 = x0 + lx, gy = y0 + ty;

    u64 dup[48];
    #pragma unroll
    for (int c = 0; c < 4; c++)
        #pragma unroll
        for (int r = 0; r < 3; r++)
            #pragma unroll
            for (int k = 0; k < 4; k++)
                dup[c*12 + r*4 + k] = dup2(s_in[(c*TH + ty + r*S)*TW + lx + k*S]);

    float* outp = g_hid + ((size_t)z*FF << 16) + (gy<<8) + gx0;
    #pragma unroll 2
    for (int op = 0; op < 64; op++) {
        u64 a0 = *(const u64*)&s_b[2*op];
        u64 a1 = a0;
        #pragma unroll
        for (int c = 0; c < 4; c++)
            #pragma unroll
            for (int ky = 0; ky < 3; ky++)
                #pragma unroll
                for (int kx = 0; kx < 3; kx++) {
                    u64 w2 = *(const u64*)&s_wt[(c*9 + ky*3 + kx)*FF + 2*op];
                    fma2(a0, dup[c*12 + ky*4 + kx],     w2);
                    fma2(a1, dup[c*12 + ky*4 + kx + 1], w2);
                }
        outp[(size_t)(2*op)   << 16]       = fmaxf(lo2(a0), 0.f);
        outp[(size_t)(2*op+1) << 16]       = fmaxf(hi2(a0), 0.f);
        outp[((size_t)(2*op)   << 16) + S] = fmaxf(lo2(a1), 0.f);
        outp[((size_t)(2*op+1) << 16) + S] = fmaxf(hi2(a1), 0.f);
    }
}

// ---------------- conv 128 -> 4, K-QUARTER split ------------------------------
// grid (8,16,16): z = kq*4 + br*2 + b. Each block contracts 32 ic (8 chunks).
// cp.async staging + hoisted offsets (R14/R15 proven inner loop).
template<int S>
__device__ __forceinline__ void f2c_run(
    float* s_act, float* s_w,
    float bias0, float bias1, float bias2, float bias3,
    const float* __restrict__ actbase, float* __restrict__ out,
    int b, int x0, int y0, int tid)
{
    constexpr int TW = 36, TH = 20;
    constexpr int CH = 4, NCHUNK = 32/CH;   // 8 chunks (32 ic per block)
    constexpr int NACT = CH*TH*TW;          // 2880
    constexpr int PREN = (NACT + 127)/128;  // 23
    constexpr u32 INVALID = 0xFFFFFFFFu;

    const int tx = tid & 7, ty = tid >> 3;
    const int lx = 4*tx;
    const u32 s_act_u32 = (u32)__cvta_generic_to_shared(s_act);

    // hoisted, chunk-invariant staging element-offsets (computed once)
    u32 off[PREN];
    {
        int n = 0;
        for (int i = tid; i < NACT; i += 128, n++) {
            int c = i/(TH*TW), r = i%(TH*TW), sy = r/TW, sx = r%TW;
            int gy = y0+sy-S, gx = x0+sx-S;
            bool ok = (gy >= 0 && gy < HH && gx >= 0 && gx < WW);
            off[n] = ok ? (u32)((c<<16) + (gy<<8) + gx) : INVALID;
        }
        for (; n < PREN; n++) off[n] = INVALID;
    }

    u64 a01[4], a23[4];   // per px p: (oc0,oc1) and (oc2,oc3)
    {
        u64 b01 = pack2(bias0, bias1);
        u64 b23 = pack2(bias2, bias3);
        #pragma unroll
        for (int p = 0; p < 4; p++) { a01[p] = b01; a23[p] = b23; }
    }

    auto stage = [&](u32 sbuf, const float* nb) {
        #pragma unroll
        for (int n = 0; n < PREN; n++) {
            int i = tid + n*128;
            if (i < NACT) {
                bool ok = (off[n] != INVALID);
                const float* gp = ok ? nb + off[n] : nb;
                asm volatile("cp.async.ca.shared.global [%0], [%1], 4, %2;"
                             :: "r"(sbuf + (u32)(i*4)), "l"(gp), "r"(ok ? 4 : 0)
                             : "memory");
            }
        }
        asm volatile("cp.async.commit_group;" ::: "memory");
    };

    // prologue: stage chunk 0 into buffer 0
    stage(s_act_u32, actbase);

    for (int ck = 0; ck < NCHUNK; ck++) {
        asm volatile("cp.async.wait_group 0;" ::: "memory");
        __syncthreads();
        if (ck + 1 < NCHUNK) {
            const float* nb = actbase + ((size_t)((ck+1)*CH) << 16);
            stage(s_act_u32 + (u32)(((ck+1) & 1) * NACT * 4), nb);
        }
        const float* buf = s_act + (ck & 1) * NACT;
        #pragma unroll
        for (int c = 0; c < CH; c++) {
            const int icl = ck*CH + c;   // local ic index 0..31 into s_w
            #pragma unroll
            for (int r = 0; r < 3; r++) {
                const float* rowp = &buf[(c*TH + ty + r*S)*TW + lx];
                float4 q0 = *(const float4*)rowp;       // cols lx..lx+3
                float4 q1 = *(const float4*)(rowp + 4); // cols lx+4..lx+7
                u64 dd[8];
                dd[0] = dup2(q0.x); dd[1] = dup2(q0.y);
                dd[2] = dup2(q0.z); dd[3] = dup2(q0.w);
                dd[4] = dup2(q1.x); dd[5] = dup2(q1.y);
                dd[6] = dup2(q1.z); dd[7] = dup2(q1.w);
                #pragma unroll
                for (int k = 0; k < 3; k++) {
                    longlong2 wv = *(const longlong2*)&s_w[(icl*9 + r*3 + k)*4];
                    #pragma unroll
                    for (int p = 0; p < 4; p++) {
                        fma2(a01[p], dd[p + k*S], (u64)wv.x);
                        fma2(a23[p], dd[p + k*S], (u64)wv.y);
                    }
                }
            }
        }
    }

    const int gx0 = x0 + lx, gy = y0 + ty;
    size_t base = ((size_t)b*CC << 16) + (gy<<8) + gx0;
    float4 v0 = make_float4(lo2(a01[0]), lo2(a01[1]), lo2(a01[2]), lo2(a01[3]));
    float4 v1 = make_float4(hi2(a01[0]), hi2(a01[1]), hi2(a01[2]), hi2(a01[3]));
    float4 v2 = make_float4(lo2(a23[0]), lo2(a23[1]), lo2(a23[2]), lo2(a23[3]));
    float4 v3 = make_float4(hi2(a23[0]), hi2(a23[1]), hi2(a23[2]), hi2(a23[3]));
    *(float4*)&out[base]                     = v0;
    *(float4*)&out[base + ((size_t)1 << 16)] = v1;
    *(float4*)&out[base + ((size_t)2 << 16)] = v2;
    *(float4*)&out[base + ((size_t)3 << 16)] = v3;
}

__global__ void __launch_bounds__(128) k_f2c(
    const float* __restrict__ w_su, const float* __restrict__ b_su,
    const float* __restrict__ w_nu, const float* __restrict__ b_nu)
{
    constexpr int NACT = 4*20*36;           // 2880
    extern __shared__ float smem[];
    float* s_act = smem;                    // 2 x 2880 floats (23KB ping-pong)
    float* s_w   = smem + 2*NACT;           // 32*9*4 = 1152 floats (4.5KB)
    const int tid = threadIdx.x;
    const int z = blockIdx.z;
    const int kq = z >> 2;                  // ic quarter: 0..3
    const int br = (z >> 1) & 1, b = z & 1;
    const int icbase = kq * 32;
    const float* w    = br ? w_nu : w_su;
    const float* bias = br ? b_nu : b_su;
    float* out = br ? g_nbrq[kq] : g_updq[kq];
    const float* actbase = g_hid + ((size_t)(br*BB+b)*FF << 16) + ((size_t)icbase << 16);
    const int x0 = blockIdx.x*32, y0 = blockIdx.y*16;

    // weights for this ic quarter: [icl][kj][oc], icl = 0..31
    for (int i = tid; i < CC*32*9; i += 128) {
        int oc = i & 3, t = i >> 2;
        int icl = t / 9, kj = t % 9;
        s_w[i] = w[((size_t)oc*FF + icbase + icl)*9 + kj];
    }
    __syncthreads();   // weights ready before compute reads them

    float b0 = kq ? 0.f : bias[0];
    float b1 = kq ? 0.f : bias[1];
    float b2 = kq ? 0.f : bias[2];
    float b3 = kq ? 0.f : bias[3];

    if (br == 0) f2c_run<1>(s_act, s_w, b0, b1, b2, b3, actbase, out, b, x0, y0, tid);
    else         f2c_run<2>(s_act, s_w, b0, b1, b2, b3, actbase, out, b, x0, y0, tid);
}

// ---------------- fused gradient-magnitude + box sums + similarity ------------
__global__ void k_iter_a(const float* __restrict__ state,
                         const float* __restrict__ skx, const float* __restrict__ sky)
{
    __shared__ float s_st[22*22];
    __shared__ float s_gm[20*20];
    __shared__ float red[256];
    const int bc = blockIdx.z;
    const int c = bc & 3;
    const int x0 = blockIdx.x*16, y0 = blockIdx.y*16;
    const int tid = threadIdx.x;
    const float* sp = state + ((size_t)bc << 16);

    for (int i = tid; i < 22*22; i += 256) {
        int sy = i/22, sx = i%22;
        int gy = y0+sy-3, gx = x0+sx-3;
        float v = 0.f;
        if (gy >= 0 && gy < HH && gx >= 0 && gx < WW) v = sp[(gy<<8) + gx];
        s_st[i] = v;
    }
    float kx[9], ky[9];
    #pragma unroll
    for (int j = 0; j < 9; j++) { kx[j] = skx[c*9+j]; ky[j] = sky[c*9+j]; }
    __syncthreads();

    for (int i = tid; i < 20*20; i += 256) {
        int sy = i/20, sx = i%20;
        int gy = y0+sy-2, gx = x0+sx-2;
        float v = 0.f;
        if (gy >= 0 && gy < HH && gx >= 0 && gx < WW) {
            float ax = 0.f, ay = 0.f;
            #pragma unroll
            for (int dy = 0; dy < 3; dy++)
                #pragma unroll
                for (int dx = 0; dx < 3; dx++) {
                    float s = s_st[(sy+dy)*22 + sx+dx];
                    ax += s * kx[dy*3+dx];
                    ay += s * ky[dy*3+dx];
                }
            v = sqrtf(ax*ax + ay*ay);
        }
        s_gm[i] = v;
    }
    __syncthreads();

    const int tx = tid & 15, ty = tid >> 4;
    float g0 = s_gm[(ty+2)*20 + tx+2];
    float s1 = 0.f, s2 = 0.f, s3 = 0.f;
    #pragma unroll
    for (int dy = 0; dy < 5; dy++)
        #pragma unroll
        for (int dx = 0; dx < 5; dx++) {
            float g = s_gm[(ty+dy)*20 + tx+dx];
            s1 += g; s2 += g*g;
            s3 += s_st[(ty+1+dy)*22 + tx+1+dx];
        }
    float dist = s2 - 2.f*g0*s1 + 25.f*g0*g0;
    float sv = expf(-2.f*dist);
    size_t oi = ((size_t)bc << 16) + ((y0+ty)<<8) + (x0+tx);
    g_sim[oi]   = sv;
    g_boxst[oi] = s3;

    red[tid] = sv; __syncthreads();
    for (int o = 128; o > 0; o >>= 1) { if (tid < o) red[tid] += red[tid+o]; __syncthreads(); }
    if (tid == 0) atomicAdd(&g_simsum[bc], red[0]);
}

// ---------------- fused dynamic conv + combine (ping-pong state) --------------
__global__ void k_iter_b(const float* __restrict__ state, float* __restrict__ nstate,
                         const float* __restrict__ w, const float* __restrict__ bias)
{
    __shared__ float s_st[4*18*18];
    __shared__ float s_w[144];
    __shared__ float s_b[4];
    const int b = blockIdx.z;
    const int x0 = blockIdx.x*16, y0 = blockIdx.y*16;
    const int tid = threadIdx.x;

    if (tid < 144) s_w[tid] = w[tid];
    if (tid < 4)   s_b[tid] = bias[tid];
    for (int i = tid; i < 4*18*18; i += 256) {
        int c = i/324, r = i%324, sy = r/18, sx = r%18;
        int gy = y0+sy-1, gx = x0+sx-1;
        float v = 0.f;
        if (gy >= 0 && gy < HH && gx >= 0 && gx < WW)
            v = state[((size_t)(b*4+c) << 16) + (gy<<8) + gx];
        s_st[i] = v;
    }
    __syncthreads();

    const int tx = tid & 15, ty = tid >> 4;
    float hf[4] = { s_b[0], s_b[1], s_b[2], s_b[3] };
    #pragma unroll
    for (int ic = 0; ic < 4; ic++) {
        float v[9];
        #pragma unroll
        for (int dy = 0; dy < 3; dy++)
            #pragma unroll
            for (int dx = 0; dx < 3; dx++)
                v[dy*3+dx] = s_st[ic*324 + (ty+dy)*18 + tx+dx];
        #pragma unroll
        for (int oc = 0; oc < 4; oc++)
            #pragma unroll
            for (int j = 0; j < 9; j++)
                hf[oc] += v[j] * s_w[(oc*4+ic)*9 + j];
    }

    #pragma unroll
    for (int cc = 0; cc < 4; cc++) {
        size_t idx = ((size_t)(b*4+cc) << 16) + ((y0+ty)<<8) + (x0+tx);
        float inv = 1.f/(g_simsum[b*4+cc] + 1e-8f);
        float upd = (g_updq[0][idx] + g_updq[1][idx]) + (g_updq[2][idx] + g_updq[3][idx]);
        float nbr = (g_nbrq[0][idx] + g_nbrq[1][idx]) + (g_nbrq[2][idx] + g_nbrq[3][idx]);
        nstate[idx] = g_sim[idx]*inv*g_boxst[idx] + upd + nbr + hf[cc];
    }
}

// ---------------- fused final: gm + hf + selection + loss ---------------------
__global__ void k_final(const float* __restrict__ state, const int* __restrict__ tgt,
                        const float* __restrict__ dw, const float* __restrict__ db,
                        const float* __restrict__ skx, const float* __restrict__ sky,
                        float* __restrict__ out)
{
    __shared__ float s_st[4*18*18];
    __shared__ float s_w[144];
    __shared__ float s_b[4];
    __shared__ float s_k[2*36];
    __shared__ float red[256];
    const int b = blockIdx.z;
    const int x0 = blockIdx.x*16, y0 = blockIdx.y*16;
    const int tid = threadIdx.x;

    if (tid < 144) s_w[tid] = dw[tid];
    if (tid < 4)   s_b[tid] = db[tid];
    if (tid < 36)  s_k[tid] = skx[tid];
    if (tid >= 36 && tid < 72) s_k[tid] = sky[tid-36];
    for (int i = tid; i < 4*18*18; i += 256) {
        int c = i/324, r = i%324, sy = r/18, sx = r%18;
        int gy = y0+sy-1, gx = x0+sx-1;
        float v = 0.f;
        if (gy >= 0 && gy < HH && gx >= 0 && gx < WW)
            v = state[((size_t)(b*4+c) << 16) + (gy<<8) + gx];
        s_st[i] = v;
    }
    __syncthreads();

    const int tx = tid & 15, ty = tid >> 4;
    const int t = tgt[b];
    float lsum = 0.f;

    float hf[4] = { s_b[0], s_b[1], s_b[2], s_b[3] };
    #pragma unroll
    for (int ic = 0; ic < 4; ic++) {
        float v[9];
        #pragma unroll
        for (int dy = 0; dy < 3; dy++)
            #pragma unroll
            for (int dx = 0; dx < 3; dx++)
                v[dy*3+dx] = s_st[ic*324 + (ty+dy)*18 + tx+dx];
        #pragma unroll
        for (int oc = 0; oc < 4; oc++)
            #pragma unroll
            for (int j = 0; j < 9; j++)
                hf[oc] += v[j] * s_w[(oc*4+ic)*9 + j];
    }

    #pragma unroll
    for (int c = 0; c < 4; c++) {
        float ax = 0.f, ay = 0.f;
        #pragma unroll
        for (int dy = 0; dy < 3; dy++)
            #pragma unroll
            for (int dx = 0; dx < 3; dx++) {
                float s = s_st[c*324 + (ty+dy)*18 + tx+dx];
                ax += s * s_k[c*9 + dy*3+dx];
                ay += s * s_k[36 + c*9 + dy*3+dx];
            }
        float gmv = sqrtf(ax*ax + ay*ay);
        float hfs = sigm(hf[c]);
        float sg  = sigm(gmv);
        float pos, neg;
        if      (t == 0) { pos = hfs;     neg = 1.f - sg;      }
        else if (t == 1) { pos = sg;      neg = 1.f - hfs;     }
        else if (t == 2) { pos = hfs*sg;  neg = 1.f - hfs*sg;  }
        else             { float q = sigm(gmv*hfs); pos = q; neg = 1.f - q; }
        pos = fminf(fmaxf(pos, 0.f), 1.f);
        neg = fminf(fmaxf(neg, 0.f), 1.f);
        float ep = expf(pos), en = expf(neg);
        float sel = ep / (ep + en + 1e-8f);
        size_t idx = ((size_t)(b*4+c) << 16) + ((y0+ty)<<8) + (x0+tx);
        out[idx] = state[idx] * sel;
        lsum += sel*neg + (1.f - sel)*pos;
    }

    red[tid] = lsum; __syncthreads();
    for (int o = 128; o > 0; o >>= 1) { if (tid < o) red[tid] += red[tid+o]; __syncthreads(); }
    if (tid == 0) atomicAdd(&g_loss, red[0]);
}

__global__ void k_write_loss(float* __restrict__ out)
{
    if (threadIdx.x == 0) out[NTOT] = g_loss * (1.f/(float)NTOT);
}

// ---------------- launcher -----------------------------------------------------
extern "C" void kernel_launch(void* const* d_in, const int* in_sizes, int n_in,
                              void* d_out, int out_size)
{
    const float* x      = (const float*)d_in[0];
    const int*   tgt    = (const int*)  d_in[1];
    const float* fc_w   = (const float*)d_in[2];
    const float* fc_b   = (const float*)d_in[3];
    const float* modw   = (const float*)d_in[4];
    const float* su_w1  = (const float*)d_in[5];
    const float* su_b1  = (const float*)d_in[6];
    const float* su_w2  = (const float*)d_in[7];
    const float* su_b2  = (const float*)d_in[8];
    const float* nu_w1  = (const float*)d_in[9];
    const float* nu_b1  = (const float*)d_in[10];
    const float* nu_w2  = (const float*)d_in[11];
    const float* nu_b2  = (const float*)d_in[12];
    const float* dc_w   = (const float*)d_in[13];
    const float* dc_b   = (const float*)d_in[14];
    const float* sob_kx = (const float*)d_in[15];
    const float* sob_ky = (const float*)d_in[16];
    float* out = (float*)d_out;

    float *pA, *pB;
    cudaGetSymbolAddress((void**)&pA, g_stateA);
    cudaGetSymbolAddress((void**)&pB, g_stateB);

    // dynamic smem for f2c: 2*2880 + 1152 floats = 27648 B
    const int smemF = (2*2880 + 1152)*4;
    cudaFuncSetAttribute(k_f2c, cudaFuncAttributeMaxDynamicSharedMemorySize, smemF);

    const dim3 cgrid(8, 16, 4);        // c2f tiles 32x16, z = branch*BB+b
    const dim3 fgrid(8, 16, 16);       // f2c K-quarter: z = kq*4 + branch*2 + b
    const dim3 agrid(16, 16, BB*CC);   // iter_a tiles 16x16 per (b,c)
    const dim3 bgrid(16, 16, BB);      // iter_b / final tiles 16x16 per b
    const int PW = (NTOT + 255)/256;

    k_gfeat_scale<<<BB*CC, 256>>>(x, fc_w, fc_b, modw);
    k_init<<<PW, 256>>>(x);

    float* cur = pA;
    float* nxt = pB;
    for (int it = 0; it < 3; it++) {
        k_c2f<<<cgrid, 256>>>(cur, su_w1, su_b1, nu_w1, nu_b1);
        k_f2c<<<fgrid, 128, smemF>>>(su_w2, su_b2, nu_w2, nu_b2);
        k_iter_a<<<agrid, 256>>>(cur, sob_kx, sob_ky);
        k_iter_b<<<bgrid, 256>>>(cur, nxt, dc_w, dc_b);
        float* tmpp = cur; cur = nxt; nxt = tmpp;
    }

    k_final<<<bgrid, 256>>>(cur, tgt, dc_w, dc_b, sob_kx, sob_ky, out);
    if (out_size > NTOT) k_write_loss<<<1, 32>>>(out);
}

// round 17
// speedup vs baseline: 1.3624x; 1.0223x over previous
#include <cuda_runtime.h>
#include <math.h>
#include <stdint.h>

// Problem constants
#define BB 2
#define CC 4
#define HH 256
#define WW 256
#define FF 128
#define NPIX (HH*WW)                 // 65536
#define NTOT (BB*CC*NPIX)            // 524288
#define NHID (2*BB*FF*NPIX)          // both branches: 33554432 floats (134MB)

typedef unsigned long long u64;
typedef unsigned int u32;

// ---------------- scratch (device globals; no allocation allowed) -------------
__device__ float g_stateA[NTOT];
__device__ float g_stateB[NTOT];
__device__ float g_hid[NHID];        // hidden activations, [branch*BB+b][128][HW]
__device__ float g_updq[4][NTOT];    // K-quarter partials, su branch
__device__ float g_nbrq[4][NTOT];    // K-quarter partials, nu branch
__device__ float g_sim[NTOT];
__device__ float g_boxst[NTOT];
__device__ float g_gfeat[BB*CC];
__device__ float g_scale[BB*CC];
__device__ float g_simsum[BB*CC];
__device__ float g_loss;
__device__ unsigned g_ticket;        // last-block ticket for gfeat->scale fusion
__device__ unsigned g_ticket2;       // last-block ticket for final->loss write

__device__ __forceinline__ float sigm(float v) { return 1.f/(1.f+expf(-v)); }

// ---------------- f32x2 helpers -----------------------------------------------
__device__ __forceinline__ u64 pack2(float lo, float hi) {
    u64 r; asm("mov.b64 %0, {%1, %2};" : "=l"(r) : "f"(lo), "f"(hi)); return r;
}
__device__ __forceinline__ u64 dup2(float v) { return pack2(v, v); }
__device__ __forceinline__ void fma2(u64& d, u64 a, u64 b) {
    asm("fma.rn.f32x2 %0, %1, %2, %0;" : "+l"(d) : "l"(a), "l"(b));
}
__device__ __forceinline__ float lo2(u64 v) { return __uint_as_float((unsigned)(v & 0xffffffffu)); }
__device__ __forceinline__ float hi2(u64 v) { return __uint_as_float((unsigned)(v >> 32)); }

// ---------------- gfeat + scale fused (last-block pattern) --------------------
__global__ void k_gfeat_scale(const float* __restrict__ x,
                              const float* __restrict__ fc_w,
                              const float* __restrict__ fc_b,
                              const float* __restrict__ modw)
{
    __shared__ float red[256];
    __shared__ unsigned s_last;
    int bc = blockIdx.x;
    const float* p = x + (size_t)bc*NPIX;
    float s = 0.f;
    for (int i = threadIdx.x; i < NPIX; i += 256) s += p[i];
    red[threadIdx.x] = s; __syncthreads();
    for (int o = 128; o > 0; o >>= 1) { if (threadIdx.x < o) red[threadIdx.x] += red[threadIdx.x+o]; __syncthreads(); }
    if (threadIdx.x == 0) {
        g_gfeat[bc] = red[0] * (1.f/(float)NPIX);
        __threadfence();
        s_last = atomicAdd(&g_ticket, 1u);
    }
    __syncthreads();
    if (s_last == BB*CC - 1) {   // last block computes scales
        int t = threadIdx.x;
        if (t < BB*CC) {
            int b = t / CC, c = t % CC;
            float z = fc_b[c];
            #pragma unroll
            for (int j = 0; j < CC; j++) z += g_gfeat[b*CC+j] * fc_w[c*CC+j];
            g_scale[t] = sigm(z) * sigm(modw[c]);
        }
        if (t == 0) { g_loss = 0.f; g_ticket = 0u; }  // reset for next graph replay
    }
}

// ---------------- state init ---------------------------------------------------
__global__ void k_init(const float* __restrict__ x)
{
    int i = blockIdx.x*256 + threadIdx.x;
    if (i < NTOT) g_stateA[i] = x[i] * g_scale[i >> 16];
}

// ---------------- conv 4 -> 128, 3x3, BOTH branches (runtime dilation) --------
// grid (8,16,4): z = br*BB + b. S = 1+br. Tile 32x16 px, 2 px/thread.
// AT FFMA2 ROOFLINE — do not touch.
__global__ void __launch_bounds__(256) k_c2f(
    const float* __restrict__ state,
    const float* __restrict__ w_su, const float* __restrict__ b_su,
    const float* __restrict__ w_nu, const float* __restrict__ b_nu)
{
    constexpr int TW = 36, TH = 20;     // worst case halo (S=2)
    __shared__ float s_wt[36*FF];       // [j][oc] transposed
    __shared__ float s_b[FF];
    __shared__ float s_in[CC*TH*TW];
    const int tid = threadIdx.x;
    const int z = blockIdx.z;
    const int br = z >> 1, b = z & 1;
    const int S = 1 + br;
    const float* w    = br ? w_nu : w_su;
    const float* bias = br ? b_nu : b_su;
    const int x0 = blockIdx.x*32, y0 = blockIdx.y*16;

    // zero simsum once per grid (before iter_a runs in the next launch)
    if (blockIdx.x == 0 && blockIdx.y == 0 && z == 0 && tid < BB*CC) g_simsum[tid] = 0.f;

    for (int i = tid; i < 36*FF; i += 256) {
        int oc = i & 127, j = i >> 7;
        s_wt[i] = w[oc*36 + j];
    }
    if (tid < FF) s_b[tid] = bias[tid];
    for (int i = tid; i < CC*TH*TW; i += 256) {
        int c = i/(TH*TW), r = i%(TH*TW);
        int sy = r/TW, sx = r%TW;
        int gy = y0+sy-S, gx = x0+sx-S;
        float v = 0.f;
        if (gy >= 0 && gy < HH && gx >= 0 && gx < WW)
            v = state[((size_t)(b*CC+c) << 16) + (gy<<8) + gx];
        s_in[i] = v;
    }
    __syncthreads();

    const int tx = tid & 15, ty = tid >> 4;
    const int lx = (S == 1) ? 2*tx : ((tx & 1) + (tx >> 1)*4);
    const int gx0 = x0 + lx, gy = y0 + ty;

    u64 dup[48];
    #pragma unroll
    for (int c = 0; c < 4; c++)
        #pragma unroll
        for (int r = 0; r < 3; r++)
            #pragma unroll
            for (int k = 0; k < 4; k++)
                dup[c*12 + r*4 + k] = dup2(s_in[(c*TH + ty + r*S)*TW + lx + k*S]);

    float* outp = g_hid + ((size_t)z*FF << 16) + (gy<<8) + gx0;
    #pragma unroll 2
    for (int op = 0; op < 64; op++) {
        u64 a0 = *(const u64*)&s_b[2*op];
        u64 a1 = a0;
        #pragma unroll
        for (int c = 0; c < 4; c++)
            #pragma unroll
            for (int ky = 0; ky < 3; ky++)
                #pragma unroll
                for (int kx = 0; kx < 3; kx++) {
                    u64 w2 = *(const u64*)&s_wt[(c*9 + ky*3 + kx)*FF + 2*op];
                    fma2(a0, dup[c*12 + ky*4 + kx],     w2);
                    fma2(a1, dup[c*12 + ky*4 + kx + 1], w2);
                }
        outp[(size_t)(2*op)   << 16]       = fmaxf(lo2(a0), 0.f);
        outp[(size_t)(2*op+1) << 16]       = fmaxf(hi2(a0), 0.f);
        outp[((size_t)(2*op)   << 16) + S] = fmaxf(lo2(a1), 0.f);
        outp[((size_t)(2*op+1) << 16) + S] = fmaxf(hi2(a1), 0.f);
    }
}

// ---------------- f2c inner (K-quarter, cp.async + hoisted offsets) -----------
template<int S>
__device__ __forceinline__ void f2c_run(
    float* s_act, float* s_w,
    float bias0, float bias1, float bias2, float bias3,
    const float* __restrict__ actbase, float* __restrict__ out,
    int b, int x0, int y0, int tid)
{
    constexpr int TW = 36, TH = 20;
    constexpr int CH = 4, NCHUNK = 32/CH;   // 8 chunks (32 ic per block)
    constexpr int NACT = CH*TH*TW;          // 2880
    constexpr int PREN = (NACT + 127)/128;  // 23
    constexpr u32 INVALID = 0xFFFFFFFFu;

    const int tx = tid & 7, ty = tid >> 3;
    const int lx = 4*tx;
    const u32 s_act_u32 = (u32)__cvta_generic_to_shared(s_act);

    u32 off[PREN];
    {
        int n = 0;
        for (int i = tid; i < NACT; i += 128, n++) {
            int c = i/(TH*TW), r = i%(TH*TW), sy = r/TW, sx = r%TW;
            int gy = y0+sy-S, gx = x0+sx-S;
            bool ok = (gy >= 0 && gy < HH && gx >= 0 && gx < WW);
            off[n] = ok ? (u32)((c<<16) + (gy<<8) + gx) : INVALID;
        }
        for (; n < PREN; n++) off[n] = INVALID;
    }

    u64 a01[4], a23[4];
    {
        u64 b01 = pack2(bias0, bias1);
        u64 b23 = pack2(bias2, bias3);
        #pragma unroll
        for (int p = 0; p < 4; p++) { a01[p] = b01; a23[p] = b23; }
    }

    auto stage = [&](u32 sbuf, const float* nb) {
        #pragma unroll
        for (int n = 0; n < PREN; n++) {
            int i = tid + n*128;
            if (i < NACT) {
                bool ok = (off[n] != INVALID);
                const float* gp = ok ? nb + off[n] : nb;
                asm volatile("cp.async.ca.shared.global [%0], [%1], 4, %2;"
                             :: "r"(sbuf + (u32)(i*4)), "l"(gp), "r"(ok ? 4 : 0)
                             : "memory");
            }
        }
        asm volatile("cp.async.commit_group;" ::: "memory");
    };

    stage(s_act_u32, actbase);

    for (int ck = 0; ck < NCHUNK; ck++) {
        asm volatile("cp.async.wait_group 0;" ::: "memory");
        __syncthreads();
        if (ck + 1 < NCHUNK) {
            const float* nb = actbase + ((size_t)((ck+1)*CH) << 16);
            stage(s_act_u32 + (u32)(((ck+1) & 1) * NACT * 4), nb);
        }
        const float* buf = s_act + (ck & 1) * NACT;
        #pragma unroll
        for (int c = 0; c < CH; c++) {
            const int icl = ck*CH + c;
            #pragma unroll
            for (int r = 0; r < 3; r++) {
                const float* rowp = &buf[(c*TH + ty + r*S)*TW + lx];
                float4 q0 = *(const float4*)rowp;
                float4 q1 = *(const float4*)(rowp + 4);
                u64 dd[8];
                dd[0] = dup2(q0.x); dd[1] = dup2(q0.y);
                dd[2] = dup2(q0.z); dd[3] = dup2(q0.w);
                dd[4] = dup2(q1.x); dd[5] = dup2(q1.y);
                dd[6] = dup2(q1.z); dd[7] = dup2(q1.w);
                #pragma unroll
                for (int k = 0; k < 3; k++) {
                    longlong2 wv = *(const longlong2*)&s_w[(icl*9 + r*3 + k)*4];
                    #pragma unroll
                    for (int p = 0; p < 4; p++) {
                        fma2(a01[p], dd[p + k*S], (u64)wv.x);
                        fma2(a23[p], dd[p + k*S], (u64)wv.y);
                    }
                }
            }
        }
    }

    const int gx0 = x0 + lx, gy = y0 + ty;
    size_t base = ((size_t)b*CC << 16) + (gy<<8) + gx0;
    float4 v0 = make_float4(lo2(a01[0]), lo2(a01[1]), lo2(a01[2]), lo2(a01[3]));
    float4 v1 = make_float4(hi2(a01[0]), hi2(a01[1]), hi2(a01[2]), hi2(a01[3]));
    float4 v2 = make_float4(lo2(a23[0]), lo2(a23[1]), lo2(a23[2]), lo2(a23[3]));
    float4 v3 = make_float4(hi2(a23[0]), hi2(a23[1]), hi2(a23[2]), hi2(a23[3]));
    *(float4*)&out[base]                     = v0;
    *(float4*)&out[base + ((size_t)1 << 16)] = v1;
    *(float4*)&out[base + ((size_t)2 << 16)] = v2;
    *(float4*)&out[base + ((size_t)3 << 16)] = v3;
}

// ---------------- MERGED: f2c (z<16) + iter_a (z in [16,24)) ------------------
// f2c: K-quarter split, z = kq*4 + br*2 + b (proven R16 path, untouched).
// iter_a: gm + box sums + similarity on 32x16 tiles, 128 threads, z-16 = bc.
__global__ void __launch_bounds__(128) k_f2c_a(
    const float* __restrict__ state,
    const float* __restrict__ w_su, const float* __restrict__ b_su,
    const float* __restrict__ w_nu, const float* __restrict__ b_nu,
    const float* __restrict__ skx,  const float* __restrict__ sky)
{
    constexpr int NACT = 4*20*36;           // 2880
    extern __shared__ float smem[];
    const int tid = threadIdx.x;
    const int z = blockIdx.z;
    const int x0 = blockIdx.x*32, y0 = blockIdx.y*16;

    if (z < 16) {
        // ----------------- f2c path -----------------
        float* s_act = smem;                    // 2 x 2880 floats
        float* s_w   = smem + 2*NACT;           // 1152 floats
        const int kq = z >> 2;
        const int br = (z >> 1) & 1, b = z & 1;
        const int icbase = kq * 32;
        const float* w    = br ? w_nu : w_su;
        const float* bias = br ? b_nu : b_su;
        float* out = br ? g_nbrq[kq] : g_updq[kq];
        const float* actbase = g_hid + ((size_t)(br*BB+b)*FF << 16) + ((size_t)icbase << 16);

        for (int i = tid; i < CC*32*9; i += 128) {
            int oc = i & 3, t = i >> 2;
            int icl = t / 9, kj = t % 9;
            s_w[i] = w[((size_t)oc*FF + icbase + icl)*9 + kj];
        }
        __syncthreads();

        float b0 = kq ? 0.f : bias[0];
        float b1 = kq ? 0.f : bias[1];
        float b2 = kq ? 0.f : bias[2];
        float b3 = kq ? 0.f : bias[3];

        if (br == 0) f2c_run<1>(s_act, s_w, b0, b1, b2, b3, actbase, out, b, x0, y0, tid);
        else         f2c_run<2>(s_act, s_w, b0, b1, b2, b3, actbase, out, b, x0, y0, tid);
    } else {
        // ----------------- iter_a path (32x16 tile, 128 threads) -----------------
        float* s_st = smem;                 // 22 x 38 = 836 (state, halo 3)
        float* s_gm = smem + 836;           // 20 x 36 = 720 (gm, halo 2)
        float* red  = smem + 836 + 720;     // 128
        const int bc = z - 16;              // 0..7
        const int c = bc & 3;
        const float* sp = state + ((size_t)bc << 16);

        for (int i = tid; i < 22*38; i += 128) {
            int sy = i/38, sx = i%38;
            int gy = y0+sy-3, gx = x0+sx-3;
            float v = 0.f;
            if (gy >= 0 && gy < HH && gx >= 0 && gx < WW) v = sp[(gy<<8) + gx];
            s_st[i] = v;
        }
        float kx[9], ky[9];
        #pragma unroll
        for (int j = 0; j < 9; j++) { kx[j] = skx[c*9+j]; ky[j] = sky[c*9+j]; }
        __syncthreads();

        for (int i = tid; i < 20*36; i += 128) {
            int sy = i/36, sx = i%36;
            int gy = y0+sy-2, gx = x0+sx-2;
            float v = 0.f;
            if (gy >= 0 && gy < HH && gx >= 0 && gx < WW) {
                float ax = 0.f, ay = 0.f;
                #pragma unroll
                for (int dy = 0; dy < 3; dy++)
                    #pragma unroll
                    for (int dx = 0; dx < 3; dx++) {
                        float s = s_st[(sy+dy)*38 + sx+dx];
                        ax += s * kx[dy*3+dx];
                        ay += s * ky[dy*3+dx];
                    }
                v = sqrtf(ax*ax + ay*ay);
            }
            s_gm[i] = v;
        }
        __syncthreads();

        float lsum = 0.f;
        #pragma unroll
        for (int pass = 0; pass < 4; pass++) {
            int i = tid + pass*128;            // 512 outputs = 32x16
            int oy = i >> 5, ox = i & 31;
            float g0 = s_gm[(oy+2)*36 + ox+2];
            float s1 = 0.f, s2 = 0.f, s3 = 0.f;
            #pragma unroll
            for (int dy = 0; dy < 5; dy++)
                #pragma unroll
                for (int dx = 0; dx < 5; dx++) {
                    float g = s_gm[(oy+dy)*36 + ox+dx];
                    s1 += g; s2 += g*g;
                    s3 += s_st[(oy+1+dy)*38 + ox+1+dx];
                }
            float dist = s2 - 2.f*g0*s1 + 25.f*g0*g0;
            float sv = expf(-2.f*dist);        // 1/(2*sigma^2) = 2
            size_t oi = ((size_t)bc << 16) + ((y0+oy)<<8) + (x0+ox);
            g_sim[oi]   = sv;
            g_boxst[oi] = s3;
            lsum += sv;
        }
        red[tid] = lsum; __syncthreads();
        for (int o = 64; o > 0; o >>= 1) { if (tid < o) red[tid] += red[tid+o]; __syncthreads(); }
        if (tid == 0) atomicAdd(&g_simsum[bc], red[0]);
    }
}

// ---------------- fused dynamic conv + combine (ping-pong state) --------------
__global__ void k_iter_b(const float* __restrict__ state, float* __restrict__ nstate,
                         const float* __restrict__ w, const float* __restrict__ bias)
{
    __shared__ float s_st[4*18*18];
    __shared__ float s_w[144];
    __shared__ float s_b[4];
    const int b = blockIdx.z;
    const int x0 = blockIdx.x*16, y0 = blockIdx.y*16;
    const int tid = threadIdx.x;

    if (tid < 144) s_w[tid] = w[tid];
    if (tid < 4)   s_b[tid] = bias[tid];
    for (int i = tid; i < 4*18*18; i += 256) {
        int c = i/324, r = i%324, sy = r/18, sx = r%18;
        int gy = y0+sy-1, gx = x0+sx-1;
        float v = 0.f;
        if (gy >= 0 && gy < HH && gx >= 0 && gx < WW)
            v = state[((size_t)(b*4+c) << 16) + (gy<<8) + gx];
        s_st[i] = v;
    }
    __syncthreads();

    const int tx = tid & 15, ty = tid >> 4;
    float hf[4] = { s_b[0], s_b[1], s_b[2], s_b[3] };
    #pragma unroll
    for (int ic = 0; ic < 4; ic++) {
        float v[9];
        #pragma unroll
        for (int dy = 0; dy < 3; dy++)
            #pragma unroll
            for (int dx = 0; dx < 3; dx++)
                v[dy*3+dx] = s_st[ic*324 + (ty+dy)*18 + tx+dx];
        #pragma unroll
        for (int oc = 0; oc < 4; oc++)
            #pragma unroll
            for (int j = 0; j < 9; j++)
                hf[oc] += v[j] * s_w[(oc*4+ic)*9 + j];
    }

    #pragma unroll
    for (int cc = 0; cc < 4; cc++) {
        size_t idx = ((size_t)(b*4+cc) << 16) + ((y0+ty)<<8) + (x0+tx);
        float inv = 1.f/(g_simsum[b*4+cc] + 1e-8f);
        float upd = (g_updq[0][idx] + g_updq[1][idx]) + (g_updq[2][idx] + g_updq[3][idx]);
        float nbr = (g_nbrq[0][idx] + g_nbrq[1][idx]) + (g_nbrq[2][idx] + g_nbrq[3][idx]);
        nstate[idx] = g_sim[idx]*inv*g_boxst[idx] + upd + nbr + hf[cc];
    }
}

// ---------------- fused final: gm + hf + selection + loss + loss write --------
__global__ void k_final(const float* __restrict__ state, const int* __restrict__ tgt,
                        const float* __restrict__ dw, const float* __restrict__ db,
                        const float* __restrict__ skx, const float* __restrict__ sky,
                        float* __restrict__ out, int do_loss)
{
    __shared__ float s_st[4*18*18];
    __shared__ float s_w[144];
    __shared__ float s_b[4];
    __shared__ float s_k[2*36];
    __shared__ float red[256];
    const int b = blockIdx.z;
    const int x0 = blockIdx.x*16, y0 = blockIdx.y*16;
    const int tid = threadIdx.x;

    if (tid < 144) s_w[tid] = dw[tid];
    if (tid < 4)   s_b[tid] = db[tid];
    if (tid < 36)  s_k[tid] = skx[tid];
    if (tid >= 36 && tid < 72) s_k[tid] = sky[tid-36];
    for (int i = tid; i < 4*18*18; i += 256) {
        int c = i/324, r = i%324, sy = r/18, sx = r%18;
        int gy = y0+sy-1, gx = x0+sx-1;
        float v = 0.f;
        if (gy >= 0 && gy < HH && gx >= 0 && gx < WW)
            v = state[((size_t)(b*4+c) << 16) + (gy<<8) + gx];
        s_st[i] = v;
    }
    __syncthreads();

    const int tx = tid & 15, ty = tid >> 4;
    const int t = tgt[b];
    float lsum = 0.f;

    float hf[4] = { s_b[0], s_b[1], s_b[2], s_b[3] };
    #pragma unroll
    for (int ic = 0; ic < 4; ic++) {
        float v[9];
        #pragma unroll
        for (int dy = 0; dy < 3; dy++)
            #pragma unroll
            for (int dx = 0; dx < 3; dx++)
                v[dy*3+dx] = s_st[ic*324 + (ty+dy)*18 + tx+dx];
        #pragma unroll
        for (int oc = 0; oc < 4; oc++)
            #pragma unroll
            for (int j = 0; j < 9; j++)
                hf[oc] += v[j] * s_w[(oc*4+ic)*9 + j];
    }

    #pragma unroll
    for (int c = 0; c < 4; c++) {
        float ax = 0.f, ay = 0.f;
        #pragma unroll
        for (int dy = 0; dy < 3; dy++)
            #pragma unroll
            for (int dx = 0; dx < 3; dx++) {
                float s = s_st[c*324 + (ty+dy)*18 + tx+dx];
                ax += s * s_k[c*9 + dy*3+dx];
                ay += s * s_k[36 + c*9 + dy*3+dx];
            }
        float gmv = sqrtf(ax*ax + ay*ay);
        float hfs = sigm(hf[c]);
        float sg  = sigm(gmv);
        float pos, neg;
        if      (t == 0) { pos = hfs;     neg = 1.f - sg;      }
        else if (t == 1) { pos = sg;      neg = 1.f - hfs;     }
        else if (t == 2) { pos = hfs*sg;  neg = 1.f - hfs*sg;  }
        else             { float q = sigm(gmv*hfs); pos = q; neg = 1.f - q; }
        pos = fminf(fmaxf(pos, 0.f), 1.f);
        neg = fminf(fmaxf(neg, 0.f), 1.f);
        float ep = expf(pos), en = expf(neg);
        float sel = ep / (ep + en + 1e-8f);
        size_t idx = ((size_t)(b*4+c) << 16) + ((y0+ty)<<8) + (x0+tx);
        out[idx] = state[idx] * sel;
        lsum += sel*neg + (1.f - sel)*pos;
    }

    red[tid] = lsum; __syncthreads();
    for (int o = 128; o > 0; o >>= 1) { if (tid < o) red[tid] += red[tid+o]; __syncthreads(); }
    if (tid == 0) {
        atomicAdd(&g_loss, red[0]);
        if (do_loss) {
            __threadfence();
            unsigned last = atomicAdd(&g_ticket2, 1u);
            if (last == 16*16*BB - 1) {   // last block writes loss scalar
                out[NTOT] = g_loss * (1.f/(float)NTOT);
                g_ticket2 = 0u;           // reset for next graph replay
            }
        }
    }
}

// ---------------- launcher -----------------------------------------------------
extern "C" void kernel_launch(void* const* d_in, const int* in_sizes, int n_in,
                              void* d_out, int out_size)
{
    const float* x      = (const float*)d_in[0];
    const int*   tgt    = (const int*)  d_in[1];
    const float* fc_w   = (const float*)d_in[2];
    const float* fc_b   = (const float*)d_in[3];
    const float* modw   = (const float*)d_in[4];
    const float* su_w1  = (const float*)d_in[5];
    const float* su_b1  = (const float*)d_in[6];
    const float* su_w2  = (const float*)d_in[7];
    const float* su_b2  = (const float*)d_in[8];
    const float* nu_w1  = (const float*)d_in[9];
    const float* nu_b1  = (const float*)d_in[10];
    const float* nu_w2  = (const float*)d_in[11];
    const float* nu_b2  = (const float*)d_in[12];
    const float* dc_w   = (const float*)d_in[13];
    const float* dc_b   = (const float*)d_in[14];
    const float* sob_kx = (const float*)d_in[15];
    const float* sob_ky = (const float*)d_in[16];
    float* out = (float*)d_out;

    float *pA, *pB;
    cudaGetSymbolAddress((void**)&pA, g_stateA);
    cudaGetSymbolAddress((void**)&pB, g_stateB);

    // dynamic smem for merged f2c+iter_a: 2*2880 + 1152 floats = 27648 B
    const int smemF = (2*2880 + 1152)*4;
    cudaFuncSetAttribute(k_f2c_a, cudaFuncAttributeMaxDynamicSharedMemorySize, smemF);

    const dim3 cgrid(8, 16, 4);        // c2f tiles 32x16, z = branch*BB+b
    const dim3 fgrid(8, 16, 24);       // merged: z<16 f2c K-quarter, z>=16 iter_a
    const dim3 bgrid(16, 16, BB);      // iter_b / final tiles 16x16 per b
    const int PW = (NTOT + 255)/256;

    k_gfeat_scale<<<BB*CC, 256>>>(x, fc_w, fc_b, modw);
    k_init<<<PW, 256>>>(x);

    float* cur = pA;
    float* nxt = pB;
    for (int it = 0; it < 3; it++) {
        k_c2f<<<cgrid, 256>>>(cur, su_w1, su_b1, nu_w1, nu_b1);
        k_f2c_a<<<fgrid, 128, smemF>>>(cur, su_w2, su_b2, nu_w2, nu_b2, sob_kx, sob_ky);
        k_iter_b<<<bgrid, 256>>>(cur, nxt, dc_w, dc_b);
        float* tmpp = cur; cur = nxt; nxt = tmpp;
    }

    k_final<<<bgrid, 256>>>(cur, tgt, dc_w, dc_b, sob_kx, sob_ky, out,
                            (out_size > NTOT) ? 1 : 0);
}